// round 1
// baseline (speedup 1.0000x reference)
#include <cuda_runtime.h>

#define NB 4
#define NP 4096
#define NC 128
#define KN 16
#define TILE 1024

// scratch: knn indices (B*N*K ints = 1 MB). Device global (no allocations allowed).
__device__ int g_knn[NB * NP * KN];

// ---------------------------------------------------------------------------
// kNN: one thread per query point; candidates streamed through shared tiles.
// d2 computed with the reference formula (sq_q + sq_c) - 2*dot, strict-< top-16
// insertion so ties prefer lower candidate index (matches lax.top_k).
// ---------------------------------------------------------------------------
__global__ __launch_bounds__(128) void knn_kernel(const float* __restrict__ coords)
{
    const int b = blockIdx.y;
    const int q = blockIdx.x * blockDim.x + threadIdx.x;
    const float* cb = coords + (size_t)b * NP * 3;

    const float qx = cb[q * 3 + 0];
    const float qy = cb[q * 3 + 1];
    const float qz = cb[q * 3 + 2];
    const float qsq = qx * qx + qy * qy + qz * qz;

    float dist[KN];
    int   ind[KN];
#pragma unroll
    for (int j = 0; j < KN; ++j) { dist[j] = 3.4e38f; ind[j] = 0; }

    __shared__ float4 tile[TILE];

    for (int t0 = 0; t0 < NP; t0 += TILE) {
        __syncthreads();
        for (int i = threadIdx.x; i < TILE; i += blockDim.x) {
            const float* c = cb + (size_t)(t0 + i) * 3;
            float x = c[0], y = c[1], z = c[2];
            tile[i] = make_float4(x, y, z, x * x + y * y + z * z);
        }
        __syncthreads();
#pragma unroll 4
        for (int i = 0; i < TILE; ++i) {
            float4 c = tile[i];
            float dot = qx * c.x + qy * c.y + qz * c.z;
            // match reference rounding: (sq_q + sq_c) - 2*dot, no fma contraction
            float d2 = __fsub_rn(__fadd_rn(qsq, c.w), __fmul_rn(2.0f, dot));
            if (d2 < dist[KN - 1]) {          // rare path (~105 inserts / 4096)
                float dc = d2;
                int   ic = t0 + i;
#pragma unroll
                for (int j = 0; j < KN; ++j) {
                    if (dc < dist[j]) {
                        float td = dist[j]; dist[j] = dc; dc = td;
                        int   ti = ind[j];  ind[j]  = ic; ic = ti;
                    }
                }
            }
        }
    }

    int* dst = g_knn + ((size_t)b * NP + q) * KN;
#pragma unroll
    for (int j = 0; j < KN; ++j) dst[j] = ind[j];
}

// ---------------------------------------------------------------------------
// Fused point-transformer kernel.
// One block = 2 points (amortizes phi/g1/g2 weight traffic). 128 threads,
// thread o owns output channel o. att matrix (32 rows = 2 points x 16 knn,
// 128 channels) lives in shared as att_sh[channel][row] with pad 36 so the
// gamma-MLP inner loop is float4 broadcast LDS + FFMA (FFMA-pipe bound).
// ---------------------------------------------------------------------------
__global__ __launch_bounds__(128) void pt_kernel(
    const float* __restrict__ coords,
    const float* __restrict__ features,
    const float* __restrict__ phi_w,  const float* __restrict__ phi_b,
    const float* __restrict__ psi_w,  const float* __restrict__ psi_b,
    const float* __restrict__ g1_w,   const float* __restrict__ g1_b,
    const float* __restrict__ g2_w,   const float* __restrict__ g2_b,
    const float* __restrict__ s1_w,   const float* __restrict__ s1_b,
    const float* __restrict__ s2_w,   const float* __restrict__ s2_b,
    const float* __restrict__ alpha_w, const float* __restrict__ alpha_b,
    float* __restrict__ out)
{
    const int o   = threadIdx.x;          // channel 0..127
    const int pn0 = blockIdx.x * 2;       // first of 2 points handled here
    const int b   = pn0 >> 12;            // /4096
    const int n0  = pn0 & (NP - 1);

    __shared__ __align__(16) float att_sh[NC][36];  // [channel][pk], pad 36
    __shared__ float f_sh[2][NC];
    __shared__ float kc_sh[32][3];
    __shared__ float qc_sh[2][3];
    __shared__ float sm_m[32], sm_inv[32];

    // ---- loads ----
    f_sh[0][o] = features[((size_t)(b * NP + n0)) * NC + o];
    f_sh[1][o] = features[((size_t)(b * NP + n0 + 1)) * NC + o];
    if (o < 32) {
        int p  = o >> 4;
        int id = g_knn[((size_t)(b * NP + n0 + p)) * KN + (o & 15)];
        const float* c = coords + ((size_t)(b * NP) + id) * 3;
        kc_sh[o][0] = c[0]; kc_sh[o][1] = c[1]; kc_sh[o][2] = c[2];
    }
    if (o < 6) {
        int p = o / 3;
        qc_sh[p][o % 3] = coords[((size_t)(b * NP + n0 + p)) * 3 + (o % 3)];
    }

    // per-thread small weights (row o of each 3->C linear, plus s1 full)
    const float psw0 = psi_w[o * 3 + 0], psw1 = psi_w[o * 3 + 1], psw2 = psi_w[o * 3 + 2], psb = psi_b[o];
    const float s2w0 = s2_w[o * 3 + 0],  s2w1 = s2_w[o * 3 + 1],  s2w2 = s2_w[o * 3 + 2],  s2b = s2_b[o];
    const float aw0 = alpha_w[o * 3 + 0], aw1 = alpha_w[o * 3 + 1], aw2 = alpha_w[o * 3 + 2], ab = alpha_b[o];
    const float g1b = g1_b[o], g2b = g2_b[o];
    const float s100 = s1_w[0], s101 = s1_w[1], s102 = s1_w[2];
    const float s110 = s1_w[3], s111 = s1_w[4], s112 = s1_w[5];
    const float s120 = s1_w[6], s121 = s1_w[7], s122 = s1_w[8];
    const float s1b0 = s1_b[0], s1b1 = s1_b[1], s1b2 = s1_b[2];

    __syncthreads();

    // ---- xi = phi(features), thread o computes channel o for both points ----
    float xi0 = phi_b[o];
    float xi1 = xi0;
    {
        const float4* pw = (const float4*)(phi_w + (size_t)o * NC);
#pragma unroll 8
        for (int i4 = 0; i4 < NC / 4; ++i4) {
            float4 w = pw[i4];
            int i = i4 * 4;
            xi0 = fmaf(w.x, f_sh[0][i + 0], xi0);
            xi0 = fmaf(w.y, f_sh[0][i + 1], xi0);
            xi0 = fmaf(w.z, f_sh[0][i + 2], xi0);
            xi0 = fmaf(w.w, f_sh[0][i + 3], xi0);
            xi1 = fmaf(w.x, f_sh[1][i + 0], xi1);
            xi1 = fmaf(w.y, f_sh[1][i + 1], xi1);
            xi1 = fmaf(w.z, f_sh[1][i + 2], xi1);
            xi1 = fmaf(w.w, f_sh[1][i + 3], xi1);
        }
    }

    // ---- att0 = xi - psi(kc) + pos, pos kept in registers ----
    float pos_r[32];
#pragma unroll
    for (int pk = 0; pk < 32; ++pk) {
        int p = pk >> 4;
        float cx = kc_sh[pk][0], cy = kc_sh[pk][1], cz = kc_sh[pk][2];
        float rx = qc_sh[p][0] - cx, ry = qc_sh[p][1] - cy, rz = qc_sh[p][2] - cz;
        float h0 = fmaxf(s100 * rx + s101 * ry + s102 * rz + s1b0, 0.0f);
        float h1 = fmaxf(s110 * rx + s111 * ry + s112 * rz + s1b1, 0.0f);
        float h2 = fmaxf(s120 * rx + s121 * ry + s122 * rz + s1b2, 0.0f);
        float pos = s2w0 * h0 + s2w1 * h1 + s2w2 * h2 + s2b;
        pos_r[pk] = pos;
        float xj = psw0 * cx + psw1 * cy + psw2 * cz + psb;
        att_sh[o][pk] = (p ? xi1 : xi0) - xj + pos;
    }
    __syncthreads();

    float acc[32];

    // ---- gamma layer 1: acc[pk] = g1_w[o,:] . att[:, pk] + g1_b[o] ----
#pragma unroll
    for (int pk = 0; pk < 32; ++pk) acc[pk] = g1b;
    {
        const float4* wr = (const float4*)(g1_w + (size_t)o * NC);
        for (int i4 = 0; i4 < NC / 4; ++i4) {
            float4 w = wr[i4];
#pragma unroll
            for (int u = 0; u < 4; ++u) {
                float wi = (u == 0) ? w.x : (u == 1) ? w.y : (u == 2) ? w.z : w.w;
                const float4* row = (const float4*)att_sh[i4 * 4 + u];
#pragma unroll
                for (int qq = 0; qq < 8; ++qq) {
                    float4 a = row[qq];
                    acc[qq * 4 + 0] = fmaf(wi, a.x, acc[qq * 4 + 0]);
                    acc[qq * 4 + 1] = fmaf(wi, a.y, acc[qq * 4 + 1]);
                    acc[qq * 4 + 2] = fmaf(wi, a.z, acc[qq * 4 + 2]);
                    acc[qq * 4 + 3] = fmaf(wi, a.w, acc[qq * 4 + 3]);
                }
            }
        }
    }
    __syncthreads();
#pragma unroll
    for (int pk = 0; pk < 32; ++pk) att_sh[o][pk] = fmaxf(acc[pk], 0.0f);  // relu
    __syncthreads();

    // ---- gamma layer 2 (no relu) ----
#pragma unroll
    for (int pk = 0; pk < 32; ++pk) acc[pk] = g2b;
    {
        const float4* wr = (const float4*)(g2_w + (size_t)o * NC);
        for (int i4 = 0; i4 < NC / 4; ++i4) {
            float4 w = wr[i4];
#pragma unroll
            for (int u = 0; u < 4; ++u) {
                float wi = (u == 0) ? w.x : (u == 1) ? w.y : (u == 2) ? w.z : w.w;
                const float4* row = (const float4*)att_sh[i4 * 4 + u];
#pragma unroll
                for (int qq = 0; qq < 8; ++qq) {
                    float4 a = row[qq];
                    acc[qq * 4 + 0] = fmaf(wi, a.x, acc[qq * 4 + 0]);
                    acc[qq * 4 + 1] = fmaf(wi, a.y, acc[qq * 4 + 1]);
                    acc[qq * 4 + 2] = fmaf(wi, a.z, acc[qq * 4 + 2]);
                    acc[qq * 4 + 3] = fmaf(wi, a.w, acc[qq * 4 + 3]);
                }
            }
        }
    }
    __syncthreads();
#pragma unroll
    for (int pk = 0; pk < 32; ++pk) att_sh[o][pk] = acc[pk];
    __syncthreads();

    // ---- softmax over CHANNELS: warp 0 computes per-row (pk) max & 1/sum ----
    if (o < 32) {
        float m = -3.4e38f;
#pragma unroll 4
        for (int i = 0; i < NC; ++i) m = fmaxf(m, att_sh[i][o]);
        float s = 0.0f;
#pragma unroll 4
        for (int i = 0; i < NC; ++i) s += expf(att_sh[i][o] - m);
        sm_m[o]   = m;
        sm_inv[o] = 1.0f / s;
    }
    __syncthreads();

    // ---- out[o] = sum_k softmax(att)[pk][o] * (alpha(kc) + pos)[pk][o] ----
    float out0 = 0.0f, out1 = 0.0f;
#pragma unroll
    for (int pk = 0; pk < 32; ++pk) {
        float e  = expf(acc[pk] - sm_m[pk]) * sm_inv[pk];
        float cx = kc_sh[pk][0], cy = kc_sh[pk][1], cz = kc_sh[pk][2];
        float v  = aw0 * cx + aw1 * cy + aw2 * cz + ab + pos_r[pk];
        if (pk < 16) out0 += e * v; else out1 += e * v;
    }
    out[((size_t)(b * NP + n0)) * NC + o]     = out0;
    out[((size_t)(b * NP + n0 + 1)) * NC + o] = out1;
}

// ---------------------------------------------------------------------------
extern "C" void kernel_launch(void* const* d_in, const int* in_sizes, int n_in,
                              void* d_out, int out_size)
{
    const float* coords   = (const float*)d_in[0];
    const float* features = (const float*)d_in[1];
    const float* phi_w    = (const float*)d_in[2];
    const float* phi_b    = (const float*)d_in[3];
    const float* psi_w    = (const float*)d_in[4];
    const float* psi_b    = (const float*)d_in[5];
    const float* g1_w     = (const float*)d_in[6];
    const float* g1_b     = (const float*)d_in[7];
    const float* g2_w     = (const float*)d_in[8];
    const float* g2_b     = (const float*)d_in[9];
    const float* s1_w     = (const float*)d_in[10];
    const float* s1_b     = (const float*)d_in[11];
    const float* s2_w     = (const float*)d_in[12];
    const float* s2_b     = (const float*)d_in[13];
    const float* alpha_w  = (const float*)d_in[14];
    const float* alpha_b  = (const float*)d_in[15];
    float* out = (float*)d_out;

    knn_kernel<<<dim3(NP / 128, NB), 128>>>(coords);
    pt_kernel<<<NB * NP / 2, 128>>>(coords, features,
                                    phi_w, phi_b, psi_w, psi_b,
                                    g1_w, g1_b, g2_w, g2_b,
                                    s1_w, s1_b, s2_w, s2_b,
                                    alpha_w, alpha_b, out);
}

// round 2
// speedup vs baseline: 1.6784x; 1.6784x over previous
#include <cuda_runtime.h>

#define NB 4
#define NP 4096
#define NC 128
#define KN 16
#define FULLM 0xFFFFFFFFu

typedef unsigned long long ull;

// scratch (no allocations allowed)
__device__ int    g_knn[NB * NP * KN];
__device__ float4 g_c4[NB * NP];

// ---------------------------------------------------------------------------
// packed f32x2 helpers (sm_100+)
// ---------------------------------------------------------------------------
__device__ __forceinline__ ull pack2(float w) {
    ull r; asm("mov.b64 %0, {%1, %1};" : "=l"(r) : "f"(w)); return r;
}
__device__ __forceinline__ void ffma2(ull& d, ull a, ull b) {
    asm("fma.rn.f32x2 %0, %1, %2, %0;" : "+l"(d) : "l"(a), "l"(b));
}

// ---------------------------------------------------------------------------
// prep: coords -> float4 (x,y,z,|c|^2)
// ---------------------------------------------------------------------------
__global__ void prep_kernel(const float* __restrict__ coords)
{
    int i = blockIdx.x * blockDim.x + threadIdx.x;
    if (i < NB * NP) {
        float x = coords[3 * i + 0], y = coords[3 * i + 1], z = coords[3 * i + 2];
        g_c4[i] = make_float4(x, y, z, x * x + y * y + z * z);
    }
}

// ---------------------------------------------------------------------------
// kNN: one WARP per query. Warp holds the sorted top-16 (one entry per lane,
// lanes 0..15 ascending). Each step every lane evaluates one candidate; a
// ballot vs tau (current 16th distance) filters; survivors are inserted via
// shfl-shift. Candidates processed in ascending index order with strict-<
// insertion => identical tie semantics to lax.top_k. d2 uses the exact
// rounding of the reference formula.
// ---------------------------------------------------------------------------
__global__ __launch_bounds__(256) void knn_kernel()
{
    const int gw   = (blockIdx.x * blockDim.x + threadIdx.x) >> 5;
    const int lane = threadIdx.x & 31;
    const int b    = gw >> 12;
    const int q    = gw & (NP - 1);

    const float4* cb = g_c4 + b * NP;
    const float4  qc = cb[q];

    float lv  = 3.4e38f;   // list value (lanes 0..15 meaningful)
    int   li  = 0;         // list index
    float tau = 3.4e38f;

    for (int t = 0; t < NP / 32; ++t) {
        const int j = t * 32 + lane;
        float4 c = __ldg(cb + j);
        float dot = qc.x * c.x + qc.y * c.y + qc.z * c.z;
        float d2  = __fsub_rn(__fadd_rn(qc.w, c.w), __fmul_rn(2.0f, dot));

        unsigned m = __ballot_sync(FULLM, d2 < tau);
        while (m) {
            int src = __ffs(m) - 1; m &= m - 1;
            float v  = __shfl_sync(FULLM, d2, src);
            int   vi = t * 32 + src;
            if (v < tau) {                       // uniform branch (v, tau uniform)
                unsigned le = __ballot_sync(FULLM, lv <= v) & 0xFFFFu;
                int pos = __popc(le);
                float upv = __shfl_up_sync(FULLM, lv, 1);
                int   upi = __shfl_up_sync(FULLM, li, 1);
                if (lane == pos)      { lv = v;   li = vi;  }
                else if (lane > pos)  { lv = upv; li = upi; }
                tau = __shfl_sync(FULLM, lv, 15);
            }
        }
    }
    if (lane < KN) g_knn[((size_t)b * NP + q) * KN + lane] = li;
}

// ---------------------------------------------------------------------------
// Fused point-transformer. Block = 4 points (64 cols = 4pts x 16 knn).
// 128 threads: thread t owns out-channels oa = t&63 and ob = oa+64, and
// col group cg = t>>6 (32 cols). Gamma GEMMs use packed fma.rn.f32x2:
// per input channel: 8 broadcast LDS.128 + 32 FFMA2 (= 64 FMA).
// ---------------------------------------------------------------------------
__global__ __launch_bounds__(128, 4) void pt_kernel(
    const float* __restrict__ features,
    const float* __restrict__ phi_w,  const float* __restrict__ phi_b,
    const float* __restrict__ psi_w,  const float* __restrict__ psi_b,
    const float* __restrict__ g1_w,   const float* __restrict__ g1_b,
    const float* __restrict__ g2_w,   const float* __restrict__ g2_b,
    const float* __restrict__ s1_w,   const float* __restrict__ s1_b,
    const float* __restrict__ s2_w,   const float* __restrict__ s2_b,
    const float* __restrict__ alpha_w, const float* __restrict__ alpha_b,
    float* __restrict__ out)
{
    const int t    = threadIdx.x;
    const int oa   = t & 63;
    const int ob   = oa + 64;
    const int cg   = t >> 6;              // 0/1 -> cols cg*32..+31
    const int pn0  = blockIdx.x * 4;
    const int b    = pn0 >> 12;
    const int n0   = pn0 & (NP - 1);
    const int base = b * NP + n0;

    __shared__ __align__(16) float att[NC][68];   // [row][col], pad 68
    __shared__ __align__(16) float fsh[4][NC];
    __shared__ float4 kc[64];
    __shared__ float4 qc[4];
    __shared__ float smp[2][64], sms[2][64], sminv[64];

    // ---- loads ----
#pragma unroll
    for (int p = 0; p < 4; ++p)
        fsh[p][t] = features[(size_t)(base + p) * NC + t];
    if (t < 64) {
        int p  = t >> 4;
        int id = g_knn[(size_t)(base + p) * KN + (t & 15)];
        kc[t]  = g_c4[b * NP + id];
    }
    if (t < 4) qc[t] = g_c4[base + t];
    __syncthreads();

    // ---- xi = phi(features) for (oa, ob) x 2 local points ----
    float xia0 = phi_b[oa], xia1 = xia0;
    float xib0 = phi_b[ob], xib1 = xib0;
    {
        const float4* wa = (const float4*)(phi_w + (size_t)oa * NC);
        const float4* wb = (const float4*)(phi_w + (size_t)ob * NC);
        const float4* f0 = (const float4*)fsh[cg * 2 + 0];
        const float4* f1 = (const float4*)fsh[cg * 2 + 1];
#pragma unroll 4
        for (int i4 = 0; i4 < NC / 4; ++i4) {
            float4 a = wa[i4], bb = wb[i4], v0 = f0[i4], v1 = f1[i4];
            xia0 = fmaf(a.x, v0.x, xia0); xia0 = fmaf(a.y, v0.y, xia0);
            xia0 = fmaf(a.z, v0.z, xia0); xia0 = fmaf(a.w, v0.w, xia0);
            xia1 = fmaf(a.x, v1.x, xia1); xia1 = fmaf(a.y, v1.y, xia1);
            xia1 = fmaf(a.z, v1.z, xia1); xia1 = fmaf(a.w, v1.w, xia1);
            xib0 = fmaf(bb.x, v0.x, xib0); xib0 = fmaf(bb.y, v0.y, xib0);
            xib0 = fmaf(bb.z, v0.z, xib0); xib0 = fmaf(bb.w, v0.w, xib0);
            xib1 = fmaf(bb.x, v1.x, xib1); xib1 = fmaf(bb.y, v1.y, xib1);
            xib1 = fmaf(bb.z, v1.z, xib1); xib1 = fmaf(bb.w, v1.w, xib1);
        }
    }

    // ---- att0 = xi - psi(kc) + pos ----
    {
        const float pa0 = psi_w[oa * 3], pa1 = psi_w[oa * 3 + 1], pa2 = psi_w[oa * 3 + 2], pab = psi_b[oa];
        const float pb0 = psi_w[ob * 3], pb1 = psi_w[ob * 3 + 1], pb2 = psi_w[ob * 3 + 2], pbb = psi_b[ob];
        const float s2a0 = s2_w[oa * 3], s2a1 = s2_w[oa * 3 + 1], s2a2 = s2_w[oa * 3 + 2], s2ab = s2_b[oa];
        const float s2b0 = s2_w[ob * 3], s2b1 = s2_w[ob * 3 + 1], s2b2 = s2_w[ob * 3 + 2], s2bb = s2_b[ob];
        const float w00 = s1_w[0], w01 = s1_w[1], w02 = s1_w[2];
        const float w10 = s1_w[3], w11 = s1_w[4], w12 = s1_w[5];
        const float w20 = s1_w[6], w21 = s1_w[7], w22 = s1_w[8];
        const float sb0 = s1_b[0], sb1 = s1_b[1], sb2 = s1_b[2];
#pragma unroll
        for (int jj = 0; jj < 32; ++jj) {
            int col = cg * 32 + jj;
            float4 c  = kc[col];
            float4 qv = qc[col >> 4];
            float rx = qv.x - c.x, ry = qv.y - c.y, rz = qv.z - c.z;
            float h0 = fmaxf(w00 * rx + w01 * ry + w02 * rz + sb0, 0.0f);
            float h1 = fmaxf(w10 * rx + w11 * ry + w12 * rz + sb1, 0.0f);
            float h2 = fmaxf(w20 * rx + w21 * ry + w22 * rz + sb2, 0.0f);
            float posa = s2a0 * h0 + s2a1 * h1 + s2a2 * h2 + s2ab;
            float posb = s2b0 * h0 + s2b1 * h1 + s2b2 * h2 + s2bb;
            float xja = pa0 * c.x + pa1 * c.y + pa2 * c.z + pab;
            float xjb = pb0 * c.x + pb1 * c.y + pb2 * c.z + pbb;
            float xa  = (jj & 16) ? xia1 : xia0;
            float xb  = (jj & 16) ? xib1 : xib0;
            att[oa][col] = xa - xja + posa;
            att[ob][col] = xb - xjb + posb;
        }
    }
    __syncthreads();

    ull ca[16], cb2[16];

    // ================= gamma layer 1 =================
    {
        ull bia = pack2(g1_b[oa]), bib = pack2(g1_b[ob]);
#pragma unroll
        for (int j = 0; j < 16; ++j) { ca[j] = bia; cb2[j] = bib; }
        const float4* wa = (const float4*)(g1_w + (size_t)oa * NC);
        const float4* wb = (const float4*)(g1_w + (size_t)ob * NC);
        for (int i4 = 0; i4 < NC / 4; ++i4) {
            float4 wa4 = wa[i4], wb4 = wb[i4];
#pragma unroll
            for (int u = 0; u < 4; ++u) {
                float wax = (u == 0) ? wa4.x : (u == 1) ? wa4.y : (u == 2) ? wa4.z : wa4.w;
                float wbx = (u == 0) ? wb4.x : (u == 1) ? wb4.y : (u == 2) ? wb4.z : wb4.w;
                ull w2a = pack2(wax), w2b = pack2(wbx);
                const ulonglong2* ar = (const ulonglong2*)&att[i4 * 4 + u][cg * 32];
#pragma unroll
                for (int j = 0; j < 8; ++j) {
                    ulonglong2 r = ar[j];
                    ffma2(ca[2 * j], w2a, r.x);  ffma2(ca[2 * j + 1], w2a, r.y);
                    ffma2(cb2[2 * j], w2b, r.x); ffma2(cb2[2 * j + 1], w2b, r.y);
                }
            }
        }
    }
    __syncthreads();
#pragma unroll
    for (int j = 0; j < 16; ++j) {
        float2 fa = *(float2*)&ca[j];
        float2 fb = *(float2*)&cb2[j];
        *(float2*)&att[oa][cg * 32 + 2 * j] = make_float2(fmaxf(fa.x, 0.0f), fmaxf(fa.y, 0.0f));
        *(float2*)&att[ob][cg * 32 + 2 * j] = make_float2(fmaxf(fb.x, 0.0f), fmaxf(fb.y, 0.0f));
    }
    __syncthreads();

    // ================= gamma layer 2 =================
    {
        ull bia = pack2(g2_b[oa]), bib = pack2(g2_b[ob]);
#pragma unroll
        for (int j = 0; j < 16; ++j) { ca[j] = bia; cb2[j] = bib; }
        const float4* wa = (const float4*)(g2_w + (size_t)oa * NC);
        const float4* wb = (const float4*)(g2_w + (size_t)ob * NC);
        for (int i4 = 0; i4 < NC / 4; ++i4) {
            float4 wa4 = wa[i4], wb4 = wb[i4];
#pragma unroll
            for (int u = 0; u < 4; ++u) {
                float wax = (u == 0) ? wa4.x : (u == 1) ? wa4.y : (u == 2) ? wa4.z : wa4.w;
                float wbx = (u == 0) ? wb4.x : (u == 1) ? wb4.y : (u == 2) ? wb4.z : wb4.w;
                ull w2a = pack2(wax), w2b = pack2(wbx);
                const ulonglong2* ar = (const ulonglong2*)&att[i4 * 4 + u][cg * 32];
#pragma unroll
                for (int j = 0; j < 8; ++j) {
                    ulonglong2 r = ar[j];
                    ffma2(ca[2 * j], w2a, r.x);  ffma2(ca[2 * j + 1], w2a, r.y);
                    ffma2(cb2[2 * j], w2b, r.x); ffma2(cb2[2 * j + 1], w2b, r.y);
                }
            }
        }
    }
    __syncthreads();
#pragma unroll
    for (int j = 0; j < 16; ++j) {
        *(float2*)&att[oa][cg * 32 + 2 * j] = *(float2*)&ca[j];
        *(float2*)&att[ob][cg * 32 + 2 * j] = *(float2*)&cb2[j];
    }
    __syncthreads();

    // ---- softmax over channels (rows), per column ----
    {
        int col = t & 63, h = t >> 6;
        float m = -3.4e38f;
#pragma unroll 8
        for (int i = h * 64; i < h * 64 + 64; ++i) m = fmaxf(m, att[i][col]);
        smp[h][col] = m;
        __syncthreads();
        m = fmaxf(smp[0][col], smp[1][col]);
        float s = 0.0f;
#pragma unroll 4
        for (int i = h * 64; i < h * 64 + 64; ++i) {
            float e = expf(att[i][col] - m);
            att[i][col] = e;
            s += e;
        }
        sms[h][col] = s;
        __syncthreads();
        if (t < 64) sminv[col] = 1.0f / (sms[0][col] + sms[1][col]);
        __syncthreads();
    }

    // ---- epilogue: out = sum_k softmax * (alpha(kc) + pos) ----
    {
        const float aa0 = alpha_w[oa * 3], aa1 = alpha_w[oa * 3 + 1], aa2 = alpha_w[oa * 3 + 2], aab = alpha_b[oa];
        const float ab0 = alpha_w[ob * 3], ab1 = alpha_w[ob * 3 + 1], ab2 = alpha_w[ob * 3 + 2], abb = alpha_b[ob];
        const float s2a0 = s2_w[oa * 3], s2a1 = s2_w[oa * 3 + 1], s2a2 = s2_w[oa * 3 + 2], s2ab = s2_b[oa];
        const float s2b0 = s2_w[ob * 3], s2b1 = s2_w[ob * 3 + 1], s2b2 = s2_w[ob * 3 + 2], s2bb = s2_b[ob];
        const float w00 = s1_w[0], w01 = s1_w[1], w02 = s1_w[2];
        const float w10 = s1_w[3], w11 = s1_w[4], w12 = s1_w[5];
        const float w20 = s1_w[6], w21 = s1_w[7], w22 = s1_w[8];
        const float sb0 = s1_b[0], sb1 = s1_b[1], sb2 = s1_b[2];

        float o0a = 0.0f, o1a = 0.0f, o0b = 0.0f, o1b = 0.0f;
#pragma unroll
        for (int jj = 0; jj < 32; ++jj) {
            int col = cg * 32 + jj;
            float4 c  = kc[col];
            float4 qv = qc[col >> 4];
            float rx = qv.x - c.x, ry = qv.y - c.y, rz = qv.z - c.z;
            float h0 = fmaxf(w00 * rx + w01 * ry + w02 * rz + sb0, 0.0f);
            float h1 = fmaxf(w10 * rx + w11 * ry + w12 * rz + sb1, 0.0f);
            float h2 = fmaxf(w20 * rx + w21 * ry + w22 * rz + sb2, 0.0f);
            float posa = s2a0 * h0 + s2a1 * h1 + s2a2 * h2 + s2ab;
            float posb = s2b0 * h0 + s2b1 * h1 + s2b2 * h2 + s2bb;
            float va = aa0 * c.x + aa1 * c.y + aa2 * c.z + aab + posa;
            float vb = ab0 * c.x + ab1 * c.y + ab2 * c.z + abb + posb;
            float iv = sminv[col];
            float ea = att[oa][col] * iv;
            float eb = att[ob][col] * iv;
            if (jj < 16) { o0a += ea * va; o0b += eb * vb; }
            else         { o1a += ea * va; o1b += eb * vb; }
        }
        int p0 = cg * 2;
        out[(size_t)(base + p0) * NC + oa]     = o0a;
        out[(size_t)(base + p0) * NC + ob]     = o0b;
        out[(size_t)(base + p0 + 1) * NC + oa] = o1a;
        out[(size_t)(base + p0 + 1) * NC + ob] = o1b;
    }
}

// ---------------------------------------------------------------------------
extern "C" void kernel_launch(void* const* d_in, const int* in_sizes, int n_in,
                              void* d_out, int out_size)
{
    const float* coords   = (const float*)d_in[0];
    const float* features = (const float*)d_in[1];
    const float* phi_w    = (const float*)d_in[2];
    const float* phi_b    = (const float*)d_in[3];
    const float* psi_w    = (const float*)d_in[4];
    const float* psi_b    = (const float*)d_in[5];
    const float* g1_w     = (const float*)d_in[6];
    const float* g1_b     = (const float*)d_in[7];
    const float* g2_w     = (const float*)d_in[8];
    const float* g2_b     = (const float*)d_in[9];
    const float* s1_w     = (const float*)d_in[10];
    const float* s1_b     = (const float*)d_in[11];
    const float* s2_w     = (const float*)d_in[12];
    const float* s2_b     = (const float*)d_in[13];
    const float* alpha_w  = (const float*)d_in[14];
    const float* alpha_b  = (const float*)d_in[15];
    float* out = (float*)d_out;

    prep_kernel<<<(NB * NP + 255) / 256, 256>>>(coords);
    knn_kernel<<<NB * NP * 32 / 256, 256>>>();
    pt_kernel<<<NB * NP / 4, 128>>>(features,
                                    phi_w, phi_b, psi_w, psi_b,
                                    g1_w, g1_b, g2_w, g2_b,
                                    s1_w, s1_b, s2_w, s2_b,
                                    alpha_w, alpha_b, out);
}

// round 3
// speedup vs baseline: 2.3987x; 1.4292x over previous
#include <cuda_runtime.h>
#include <cuda_bf16.h>

#define NB 4
#define NP 4096
#define NC 128
#define KN 16
#define FULLM 0xFFFFFFFFu

typedef unsigned int uint;

// scratch (no allocations allowed)
__device__ int    g_knn[NB * NP * KN];
__device__ float4 g_c4[NB * NP];
// split gamma weights, bf16 hi/lo, layout [m][k'] with k' = perm16 within 16-blocks
__device__ __nv_bfloat16 g_w1h[NC * NC], g_w1l[NC * NC];
__device__ __nv_bfloat16 g_w2h[NC * NC], g_w2l[NC * NC];

__device__ __host__ __forceinline__ int perm16(int i) {
    // maps k%16 so that {2t,2t+1,8+2t,8+2t+1} (one mma B/A fragment's k set)
    // become 4 contiguous halves -> 8-byte vector loads
    return ((i >> 1) & 3) * 4 + (i & 1) + ((i >> 3) << 1);
}

// ---------------------------------------------------------------------------
// prep: coords -> float4 (x,y,z,|c|^2)
// ---------------------------------------------------------------------------
__global__ void prep_kernel(const float* __restrict__ coords)
{
    int i = blockIdx.x * blockDim.x + threadIdx.x;
    if (i < NB * NP) {
        float x = coords[3 * i + 0], y = coords[3 * i + 1], z = coords[3 * i + 2];
        g_c4[i] = make_float4(x, y, z, x * x + y * y + z * z);
    }
}

// ---------------------------------------------------------------------------
// split gamma weights into bf16 hi/lo with permuted k layout
// ---------------------------------------------------------------------------
__global__ void split_kernel(const float* __restrict__ g1w, const float* __restrict__ g2w)
{
    int i = blockIdx.x * blockDim.x + threadIdx.x;
    if (i >= NC * NC) return;
    int k  = i & (NC - 1);
    int kp = (k & ~15) | perm16(k & 15);
    int j  = (i & ~(NC - 1)) | kp;
    float x = g1w[i];
    __nv_bfloat16 h = __float2bfloat16(x);
    g_w1h[j] = h;
    g_w1l[j] = __float2bfloat16(x - __bfloat162float(h));
    x = g2w[i];
    h = __float2bfloat16(x);
    g_w2h[j] = h;
    g_w2l[j] = __float2bfloat16(x - __bfloat162float(h));
}

// ---------------------------------------------------------------------------
// kNN: one WARP per query (unchanged from passing round-2 kernel)
// ---------------------------------------------------------------------------
__global__ __launch_bounds__(256) void knn_kernel()
{
    const int gw   = (blockIdx.x * blockDim.x + threadIdx.x) >> 5;
    const int lane = threadIdx.x & 31;
    const int b    = gw >> 12;
    const int q    = gw & (NP - 1);

    const float4* cb = g_c4 + b * NP;
    const float4  qc = cb[q];

    float lv  = 3.4e38f;
    int   li  = 0;
    float tau = 3.4e38f;

    for (int t = 0; t < NP / 32; ++t) {
        const int j = t * 32 + lane;
        float4 c = __ldg(cb + j);
        float dot = qc.x * c.x + qc.y * c.y + qc.z * c.z;
        float d2  = __fsub_rn(__fadd_rn(qc.w, c.w), __fmul_rn(2.0f, dot));

        unsigned m = __ballot_sync(FULLM, d2 < tau);
        while (m) {
            int src = __ffs(m) - 1; m &= m - 1;
            float v  = __shfl_sync(FULLM, d2, src);
            int   vi = t * 32 + src;
            if (v < tau) {
                unsigned le = __ballot_sync(FULLM, lv <= v) & 0xFFFFu;
                int pos = __popc(le);
                float upv = __shfl_up_sync(FULLM, lv, 1);
                int   upi = __shfl_up_sync(FULLM, li, 1);
                if (lane == pos)      { lv = v;   li = vi;  }
                else if (lane > pos)  { lv = upv; li = upi; }
                tau = __shfl_sync(FULLM, lv, 15);
            }
        }
    }
    if (lane < KN) g_knn[((size_t)b * NP + q) * KN + lane] = li;
}

// ---------------------------------------------------------------------------
// mma helper
// ---------------------------------------------------------------------------
__device__ __forceinline__ void mma16816(float (&d)[4], uint a0, uint a1, uint a2, uint a3,
                                         uint b0, uint b1)
{
    asm volatile(
        "mma.sync.aligned.m16n8k16.row.col.f32.bf16.bf16.f32 "
        "{%0,%1,%2,%3}, {%4,%5,%6,%7}, {%8,%9}, {%0,%1,%2,%3};"
        : "+f"(d[0]), "+f"(d[1]), "+f"(d[2]), "+f"(d[3])
        : "r"(a0), "r"(a1), "r"(a2), "r"(a3), "r"(b0), "r"(b1));
}

// One gamma layer, one n-group (cols ng*32..+31) for this warp (rows M0..M0+31).
// D = W(split) @ att(split) + bias, 3-term bf16 split (hh + hl + lh).
__device__ __forceinline__ void gamma_group(
    const __nv_bfloat16* __restrict__ wh, const __nv_bfloat16* __restrict__ wl,
    const float* __restrict__ bias,
    const __nv_bfloat16 (*attH)[144], const __nv_bfloat16 (*attL)[144],
    int M0, int gid, int tig, int ng, float d[2][4][4])
{
#pragma unroll
    for (int mt = 0; mt < 2; ++mt) {
        float b0 = bias[M0 + mt * 16 + gid];
        float b1 = bias[M0 + mt * 16 + gid + 8];
#pragma unroll
        for (int nt = 0; nt < 4; ++nt) {
            d[mt][nt][0] = b0; d[mt][nt][1] = b0;
            d[mt][nt][2] = b1; d[mt][nt][3] = b1;
        }
    }
#pragma unroll
    for (int ks = 0; ks < 8; ++ks) {
        const int off = ks * 16 + tig * 4;
        uint2 AH[2][2], AL[2][2];   // [mt][rowhalf]: .x = a0/a1, .y = a2/a3
#pragma unroll
        for (int mt = 0; mt < 2; ++mt) {
            int r0 = (M0 + mt * 16 + gid) * NC + off;
            AH[mt][0] = *(const uint2*)(wh + r0);
            AH[mt][1] = *(const uint2*)(wh + r0 + 8 * NC);
            AL[mt][0] = *(const uint2*)(wl + r0);
            AL[mt][1] = *(const uint2*)(wl + r0 + 8 * NC);
        }
#pragma unroll
        for (int nt = 0; nt < 4; ++nt) {
            int n = ng * 32 + nt * 8 + gid;
            uint2 bh = *(const uint2*)&attH[n][off];
            uint2 bl = *(const uint2*)&attL[n][off];
#pragma unroll
            for (int mt = 0; mt < 2; ++mt) {
                mma16816(d[mt][nt], AH[mt][0].x, AH[mt][1].x, AH[mt][0].y, AH[mt][1].y, bh.x, bh.y);
                mma16816(d[mt][nt], AH[mt][0].x, AH[mt][1].x, AH[mt][0].y, AH[mt][1].y, bl.x, bl.y);
                mma16816(d[mt][nt], AL[mt][0].x, AL[mt][1].x, AL[mt][0].y, AL[mt][1].y, bh.x, bh.y);
            }
        }
    }
}

// ---------------------------------------------------------------------------
// Fused point-transformer. Block = 4 points (64 cols), 128 threads, 4 warps.
// Gamma layers via bf16-split tensor-core mma.
// ---------------------------------------------------------------------------
// dynamic smem layout (bytes)
#define SM_ATTH 0
#define SM_ATTL 18432
#define SM_ATTF 36864              // float [128][66]
#define SM_FSH  (36864 + 33792)    // float [4][128]
#define SM_KC   (SM_FSH + 2048)    // float4 [64]
#define SM_QC   (SM_KC + 1024)     // float4 [4]
#define SM_SMP  (SM_QC + 64)       // float [2][64]
#define SM_SMS  (SM_SMP + 512)     // float [2][64]
#define SM_SMI  (SM_SMS + 512)     // float [64]
#define SM_TOTAL (SM_SMI + 256)

__global__ __launch_bounds__(128, 3) void pt_kernel(
    const float* __restrict__ features,
    const float* __restrict__ phi_w,  const float* __restrict__ phi_b,
    const float* __restrict__ psi_w,  const float* __restrict__ psi_b,
    const float* __restrict__ g1_b,   const float* __restrict__ g2_b,
    const float* __restrict__ s1_w,   const float* __restrict__ s1_b,
    const float* __restrict__ s2_w,   const float* __restrict__ s2_b,
    const float* __restrict__ alpha_w, const float* __restrict__ alpha_b,
    float* __restrict__ out)
{
    extern __shared__ __align__(16) char sm[];
    __nv_bfloat16 (*attH)[144] = (__nv_bfloat16(*)[144])(sm + SM_ATTH);
    __nv_bfloat16 (*attL)[144] = (__nv_bfloat16(*)[144])(sm + SM_ATTL);
    float (*att_f)[66] = (float(*)[66])(sm + SM_ATTF);
    float (*fsh)[NC]   = (float(*)[NC])(sm + SM_FSH);
    float4* kc         = (float4*)(sm + SM_KC);
    float4* qc         = (float4*)(sm + SM_QC);
    float (*smp)[64]   = (float(*)[64])(sm + SM_SMP);
    float (*sms)[64]   = (float(*)[64])(sm + SM_SMS);
    float* sminv       = (float*)(sm + SM_SMI);

    const int t    = threadIdx.x;
    const int c    = t & 63;          // channel-pair id / epilogue channel
    const int cg   = t >> 6;          // 0/1 -> cols cg*32..+31
    const int pn0  = blockIdx.x * 4;
    const int b    = pn0 >> 12;
    const int n0_  = pn0 & (NP - 1);
    const int base = b * NP + n0_;

    // ---- loads ----
#pragma unroll
    for (int p = 0; p < 4; ++p)
        fsh[p][t] = features[(size_t)(base + p) * NC + t];
    if (t < 64) {
        int p  = t >> 4;
        int id = g_knn[(size_t)(base + p) * KN + (t & 15)];
        kc[t]  = g_c4[b * NP + id];
    }
    if (t < 4) qc[t] = g_c4[base + t];
    __syncthreads();

    // ---- xi = phi(features): thread handles channels 2c,2c+1, points 2cg,2cg+1 ----
    const int ch0 = 2 * c, ch1 = 2 * c + 1;
    float x00 = phi_b[ch0], x01 = x00;   // ch0 x {pt even, pt odd}
    float x10 = phi_b[ch1], x11 = x10;
    {
        const float4* wa = (const float4*)(phi_w + (size_t)ch0 * NC);
        const float4* wb = (const float4*)(phi_w + (size_t)ch1 * NC);
        const float4* f0 = (const float4*)fsh[cg * 2 + 0];
        const float4* f1 = (const float4*)fsh[cg * 2 + 1];
#pragma unroll 4
        for (int i4 = 0; i4 < NC / 4; ++i4) {
            float4 a = wa[i4], bb = wb[i4], v0 = f0[i4], v1 = f1[i4];
            x00 = fmaf(a.x, v0.x, x00); x00 = fmaf(a.y, v0.y, x00);
            x00 = fmaf(a.z, v0.z, x00); x00 = fmaf(a.w, v0.w, x00);
            x01 = fmaf(a.x, v1.x, x01); x01 = fmaf(a.y, v1.y, x01);
            x01 = fmaf(a.z, v1.z, x01); x01 = fmaf(a.w, v1.w, x01);
            x10 = fmaf(bb.x, v0.x, x10); x10 = fmaf(bb.y, v0.y, x10);
            x10 = fmaf(bb.z, v0.z, x10); x10 = fmaf(bb.w, v0.w, x10);
            x11 = fmaf(bb.x, v1.x, x11); x11 = fmaf(bb.y, v1.y, x11);
            x11 = fmaf(bb.z, v1.z, x11); x11 = fmaf(bb.w, v1.w, x11);
        }
    }

    // ---- att0 = xi - psi(kc) + pos, split to bf16 hi/lo into attH/attL[col][k'] ----
    {
        const float p00 = psi_w[ch0 * 3], p01 = psi_w[ch0 * 3 + 1], p02 = psi_w[ch0 * 3 + 2], p0b = psi_b[ch0];
        const float p10 = psi_w[ch1 * 3], p11 = psi_w[ch1 * 3 + 1], p12 = psi_w[ch1 * 3 + 2], p1b = psi_b[ch1];
        const float sa0 = s2_w[ch0 * 3], sa1 = s2_w[ch0 * 3 + 1], sa2 = s2_w[ch0 * 3 + 2], sab = s2_b[ch0];
        const float sb0 = s2_w[ch1 * 3], sb1 = s2_w[ch1 * 3 + 1], sb2 = s2_w[ch1 * 3 + 2], sbb = s2_b[ch1];
        const float w00 = s1_w[0], w01 = s1_w[1], w02 = s1_w[2];
        const float w10 = s1_w[3], w11 = s1_w[4], w12 = s1_w[5];
        const float w20 = s1_w[6], w21 = s1_w[7], w22 = s1_w[8];
        const float b0s = s1_b[0], b1s = s1_b[1], b2s = s1_b[2];
        const int kp = (ch0 & ~15) | perm16(ch0 & 15);
#pragma unroll
        for (int jj = 0; jj < 32; ++jj) {
            int col = cg * 32 + jj;
            float4 cc = kc[col];
            float4 qv = qc[col >> 4];
            float rx = qv.x - cc.x, ry = qv.y - cc.y, rz = qv.z - cc.z;
            float h0 = fmaxf(w00 * rx + w01 * ry + w02 * rz + b0s, 0.0f);
            float h1 = fmaxf(w10 * rx + w11 * ry + w12 * rz + b1s, 0.0f);
            float h2 = fmaxf(w20 * rx + w21 * ry + w22 * rz + b2s, 0.0f);
            float pos0 = sa0 * h0 + sa1 * h1 + sa2 * h2 + sab;
            float pos1 = sb0 * h0 + sb1 * h1 + sb2 * h2 + sbb;
            float xj0  = p00 * cc.x + p01 * cc.y + p02 * cc.z + p0b;
            float xj1  = p10 * cc.x + p11 * cc.y + p12 * cc.z + p1b;
            float v0 = ((jj & 16) ? x01 : x00) - xj0 + pos0;
            float v1 = ((jj & 16) ? x11 : x10) - xj1 + pos1;
            __nv_bfloat16 vh0 = __float2bfloat16(v0);
            __nv_bfloat16 vh1 = __float2bfloat16(v1);
            __nv_bfloat16 vl0 = __float2bfloat16(v0 - __bfloat162float(vh0));
            __nv_bfloat16 vl1 = __float2bfloat16(v1 - __bfloat162float(vh1));
            *(uint*)&attH[col][kp] = (uint)__bfloat16_as_ushort(vh0) | ((uint)__bfloat16_as_ushort(vh1) << 16);
            *(uint*)&attL[col][kp] = (uint)__bfloat16_as_ushort(vl0) | ((uint)__bfloat16_as_ushort(vl1) << 16);
        }
    }
    __syncthreads();

    const int wid = t >> 5, lane = t & 31;
    const int gid = lane >> 2, tig = lane & 3;
    const int M0  = wid * 32;
    const int pp  = 4 * (gid >> 1) + (gid & 1);   // perm16(gid) for gid<8

    // ================= gamma layer 1 (mma, relu, split back in place) ========
    for (int ng = 0; ng < 2; ++ng) {
        float d[2][4][4];
        gamma_group(g_w1h, g_w1l, g1_b, attH, attL, M0, gid, tig, ng, d);
        __syncthreads();   // all warps done reading this group's input rows
#pragma unroll
        for (int mt = 0; mt < 2; ++mt) {
            int kb = M0 + mt * 16 + pp;
#pragma unroll
            for (int nt = 0; nt < 4; ++nt) {
                int n = ng * 32 + nt * 8 + 2 * tig;
                float v0 = fmaxf(d[mt][nt][0], 0.0f);
                float v1 = fmaxf(d[mt][nt][1], 0.0f);
                float v2 = fmaxf(d[mt][nt][2], 0.0f);
                float v3 = fmaxf(d[mt][nt][3], 0.0f);
                __nv_bfloat16 h;
                h = __float2bfloat16(v0); attH[n][kb]       = h; attL[n][kb]       = __float2bfloat16(v0 - __bfloat162float(h));
                h = __float2bfloat16(v1); attH[n + 1][kb]   = h; attL[n + 1][kb]   = __float2bfloat16(v1 - __bfloat162float(h));
                h = __float2bfloat16(v2); attH[n][kb + 2]   = h; attL[n][kb + 2]   = __float2bfloat16(v2 - __bfloat162float(h));
                h = __float2bfloat16(v3); attH[n + 1][kb + 2] = h; attL[n + 1][kb + 2] = __float2bfloat16(v3 - __bfloat162float(h));
            }
        }
        __syncthreads();
    }

    // ================= gamma layer 2 (mma -> att_f fp32) =====================
    for (int ng = 0; ng < 2; ++ng) {
        float d[2][4][4];
        gamma_group(g_w2h, g_w2l, g2_b, attH, attL, M0, gid, tig, ng, d);
#pragma unroll
        for (int mt = 0; mt < 2; ++mt) {
            int m = M0 + mt * 16 + gid;
#pragma unroll
            for (int nt = 0; nt < 4; ++nt) {
                int n = ng * 32 + nt * 8 + 2 * tig;
                *(float2*)&att_f[m][n]     = make_float2(d[mt][nt][0], d[mt][nt][1]);
                *(float2*)&att_f[m + 8][n] = make_float2(d[mt][nt][2], d[mt][nt][3]);
            }
        }
    }
    __syncthreads();

    // ---- softmax over channels (rows), per column ----
    {
        int col = t & 63, h = t >> 6;
        float m = -3.4e38f;
#pragma unroll 8
        for (int i = h * 64; i < h * 64 + 64; ++i) m = fmaxf(m, att_f[i][col]);
        smp[h][col] = m;
        __syncthreads();
        m = fmaxf(smp[0][col], smp[1][col]);
        float s = 0.0f;
#pragma unroll 4
        for (int i = h * 64; i < h * 64 + 64; ++i) {
            float e = expf(att_f[i][col] - m);
            att_f[i][col] = e;
            s += e;
        }
        sms[h][col] = s;
        __syncthreads();
        if (t < 64) sminv[col] = 1.0f / (sms[0][col] + sms[1][col]);
        __syncthreads();
    }

    // ---- epilogue: out = sum_k softmax * (alpha(kc) + pos) ----
    {
        const int oa = c, ob = c + 64;
        const float aa0 = alpha_w[oa * 3], aa1 = alpha_w[oa * 3 + 1], aa2 = alpha_w[oa * 3 + 2], aab = alpha_b[oa];
        const float ab0 = alpha_w[ob * 3], ab1 = alpha_w[ob * 3 + 1], ab2 = alpha_w[ob * 3 + 2], abb = alpha_b[ob];
        const float s2a0 = s2_w[oa * 3], s2a1 = s2_w[oa * 3 + 1], s2a2 = s2_w[oa * 3 + 2], s2ab = s2_b[oa];
        const float s2b0 = s2_w[ob * 3], s2b1 = s2_w[ob * 3 + 1], s2b2 = s2_w[ob * 3 + 2], s2bb = s2_b[ob];
        const float w00 = s1_w[0], w01 = s1_w[1], w02 = s1_w[2];
        const float w10 = s1_w[3], w11 = s1_w[4], w12 = s1_w[5];
        const float w20 = s1_w[6], w21 = s1_w[7], w22 = s1_w[8];
        const float b0s = s1_b[0], b1s = s1_b[1], b2s = s1_b[2];

        float o0a = 0.0f, o1a = 0.0f, o0b = 0.0f, o1b = 0.0f;
#pragma unroll
        for (int jj = 0; jj < 32; ++jj) {
            int col = cg * 32 + jj;
            float4 cc = kc[col];
            float4 qv = qc[col >> 4];
            float rx = qv.x - cc.x, ry = qv.y - cc.y, rz = qv.z - cc.z;
            float h0 = fmaxf(w00 * rx + w01 * ry + w02 * rz + b0s, 0.0f);
            float h1 = fmaxf(w10 * rx + w11 * ry + w12 * rz + b1s, 0.0f);
            float h2 = fmaxf(w20 * rx + w21 * ry + w22 * rz + b2s, 0.0f);
            float posa = s2a0 * h0 + s2a1 * h1 + s2a2 * h2 + s2ab;
            float posb = s2b0 * h0 + s2b1 * h1 + s2b2 * h2 + s2bb;
            float va = aa0 * cc.x + aa1 * cc.y + aa2 * cc.z + aab + posa;
            float vb = ab0 * cc.x + ab1 * cc.y + ab2 * cc.z + abb + posb;
            float iv = sminv[col];
            float ea = att_f[oa][col] * iv;
            float eb = att_f[ob][col] * iv;
            if (jj < 16) { o0a += ea * va; o0b += eb * vb; }
            else         { o1a += ea * va; o1b += eb * vb; }
        }
        int p0 = cg * 2;
        out[(size_t)(base + p0) * NC + oa]     = o0a;
        out[(size_t)(base + p0) * NC + ob]     = o0b;
        out[(size_t)(base + p0 + 1) * NC + oa] = o1a;
        out[(size_t)(base + p0 + 1) * NC + ob] = o1b;
    }
}

// ---------------------------------------------------------------------------
extern "C" void kernel_launch(void* const* d_in, const int* in_sizes, int n_in,
                              void* d_out, int out_size)
{
    const float* coords   = (const float*)d_in[0];
    const float* features = (const float*)d_in[1];
    const float* phi_w    = (const float*)d_in[2];
    const float* phi_b    = (const float*)d_in[3];
    const float* psi_w    = (const float*)d_in[4];
    const float* psi_b    = (const float*)d_in[5];
    const float* g1_w     = (const float*)d_in[6];
    const float* g1_b     = (const float*)d_in[7];
    const float* g2_w     = (const float*)d_in[8];
    const float* g2_b     = (const float*)d_in[9];
    const float* s1_w     = (const float*)d_in[10];
    const float* s1_b     = (const float*)d_in[11];
    const float* s2_w     = (const float*)d_in[12];
    const float* s2_b     = (const float*)d_in[13];
    const float* alpha_w  = (const float*)d_in[14];
    const float* alpha_b  = (const float*)d_in[15];
    float* out = (float*)d_out;

    static int smem_set = 0;
    if (!smem_set) {
        cudaFuncSetAttribute(pt_kernel, cudaFuncAttributeMaxDynamicSharedMemorySize, SM_TOTAL);
        smem_set = 1;
    }

    prep_kernel<<<(NB * NP + 255) / 256, 256>>>(coords);
    split_kernel<<<(NC * NC + 255) / 256, 256>>>(g1_w, g2_w);
    knn_kernel<<<NB * NP * 32 / 256, 256>>>();
    pt_kernel<<<NB * NP / 4, 128, SM_TOTAL>>>(features,
                                              phi_w, phi_b, psi_w, psi_b,
                                              g1_b, g2_b,
                                              s1_w, s1_b, s2_w, s2_b,
                                              alpha_w, alpha_b, out);
}

// round 5
// speedup vs baseline: 2.6948x; 1.1234x over previous
#include <cuda_runtime.h>
#include <cuda_bf16.h>

#define NB 4
#define NP 4096
#define NC 128
#define KN 16
#define FULLM 0xFFFFFFFFu

typedef unsigned int uint;
typedef unsigned short ushort;

// scratch (no allocations allowed)
__device__ int    g_knn[NB * NP * KN];
__device__ float4 g_c4[NB * NP];
// interleaved split weights: per (m, ks, tig) one uint4 = {H01, H23, L01, L23}
// where H/L cover permuted k positions 4*tig .. 4*tig+3 of 16-block ks
__device__ uint4 g_w1i[NC * 32];
__device__ uint4 g_w2i[NC * 32];

// perm16: k%16 -> position so each mma fragment's 4 halves are contiguous
// p = ((i>>1)&3)*4 + (i&1) + ((i>>3)<<1)

// ---------------------------------------------------------------------------
__global__ void prep_kernel(const float* __restrict__ coords)
{
    int i = blockIdx.x * blockDim.x + threadIdx.x;
    if (i < NB * NP) {
        float x = coords[3 * i + 0], y = coords[3 * i + 1], z = coords[3 * i + 2];
        g_c4[i] = make_float4(x, y, z, x * x + y * y + z * z);
    }
}

// ---------------------------------------------------------------------------
__global__ void split_kernel(const float* __restrict__ g1w, const float* __restrict__ g2w)
{
    int i = blockIdx.x * blockDim.x + threadIdx.x;
    if (i >= NC * NC) return;
    int m = i >> 7, k = i & 127;
    int ks = k >> 4, ii = k & 15;
    int p = ((ii >> 1) & 3) * 4 + (ii & 1) + ((ii >> 3) << 1);
    int idx = (m * 32 + ks * 4 + (p >> 2)) * 8 + (p & 3);
    ushort* w1 = (ushort*)g_w1i;
    ushort* w2 = (ushort*)g_w2i;
    float x = g1w[i];
    __nv_bfloat16 h = __float2bfloat16(x);
    w1[idx]     = __bfloat16_as_ushort(h);
    w1[idx + 4] = __bfloat16_as_ushort(__float2bfloat16(x - __bfloat162float(h)));
    x = g2w[i];
    h = __float2bfloat16(x);
    w2[idx]     = __bfloat16_as_ushort(h);
    w2[idx + 4] = __bfloat16_as_ushort(__float2bfloat16(x - __bfloat162float(h)));
}

// ---------------------------------------------------------------------------
// kNN: one WARP per query (unchanged; passing since round 2)
// ---------------------------------------------------------------------------
__global__ __launch_bounds__(256) void knn_kernel()
{
    const int gw   = (blockIdx.x * blockDim.x + threadIdx.x) >> 5;
    const int lane = threadIdx.x & 31;
    const int b    = gw >> 12;
    const int q    = gw & (NP - 1);

    const float4* cb = g_c4 + b * NP;
    const float4  qc = cb[q];

    float lv  = 3.4e38f;
    int   li  = 0;
    float tau = 3.4e38f;

    for (int t = 0; t < NP / 32; ++t) {
        const int j = t * 32 + lane;
        float4 c = __ldg(cb + j);
        float dot = qc.x * c.x + qc.y * c.y + qc.z * c.z;
        float d2  = __fsub_rn(__fadd_rn(qc.w, c.w), __fmul_rn(2.0f, dot));

        unsigned m = __ballot_sync(FULLM, d2 < tau);
        while (m) {
            int src = __ffs(m) - 1; m &= m - 1;
            float v  = __shfl_sync(FULLM, d2, src);
            int   vi = t * 32 + src;
            if (v < tau) {
                unsigned le = __ballot_sync(FULLM, lv <= v) & 0xFFFFu;
                int pos = __popc(le);
                float upv = __shfl_up_sync(FULLM, lv, 1);
                int   upi = __shfl_up_sync(FULLM, li, 1);
                if (lane == pos)      { lv = v;   li = vi;  }
                else if (lane > pos)  { lv = upv; li = upi; }
                tau = __shfl_sync(FULLM, lv, 15);
            }
        }
    }
    if (lane < KN) g_knn[((size_t)b * NP + q) * KN + lane] = li;
}

// ---------------------------------------------------------------------------
__device__ __forceinline__ void mma16816(float (&d)[4], uint a0, uint a1, uint a2, uint a3,
                                         uint b0, uint b1)
{
    asm volatile(
        "mma.sync.aligned.m16n8k16.row.col.f32.bf16.bf16.f32 "
        "{%0,%1,%2,%3}, {%4,%5,%6,%7}, {%8,%9}, {%0,%1,%2,%3};"
        : "+f"(d[0]), "+f"(d[1]), "+f"(d[2]), "+f"(d[3])
        : "r"(a0), "r"(a1), "r"(a2), "r"(a3), "r"(b0), "r"(b1));
}

// One gamma layer, full 32 rows x 64 cols for this warp, 3-term bf16 split.
// ks outer so A fragments load once (LDG.128) and feed both n-groups.
#define ATT2_STRIDE 36   // uint4 per col row; 576B = 64 mod 128 -> conflict-free

__device__ __forceinline__ void gamma_mma(
    const uint4* __restrict__ W, const float* __restrict__ bias,
    const uint4* __restrict__ att2v, int M0, int gid, int tig,
    float d[2][2][4][4])
{
#pragma unroll
    for (int mt = 0; mt < 2; ++mt) {
        float b0 = bias[M0 + mt * 16 + gid];
        float b1 = bias[M0 + mt * 16 + gid + 8];
#pragma unroll
        for (int ng = 0; ng < 2; ++ng)
#pragma unroll
        for (int nt = 0; nt < 4; ++nt) {
            d[mt][ng][nt][0] = b0; d[mt][ng][nt][1] = b0;
            d[mt][ng][nt][2] = b1; d[mt][ng][nt][3] = b1;
        }
    }
#pragma unroll
    for (int ks = 0; ks < 8; ++ks) {
        const int wo = ks * 4 + tig;
        uint4 A0 = W[(M0 + gid) * 32 + wo];          // mt0, rows gid
        uint4 A1 = W[(M0 + gid + 8) * 32 + wo];      // mt0, rows gid+8
        uint4 A2 = W[(M0 + 16 + gid) * 32 + wo];     // mt1
        uint4 A3 = W[(M0 + 16 + gid + 8) * 32 + wo];
#pragma unroll
        for (int ng = 0; ng < 2; ++ng)
#pragma unroll
        for (int nt = 0; nt < 4; ++nt) {
            int n = ng * 32 + nt * 8 + gid;
            uint4 bv = att2v[n * ATT2_STRIDE + wo];
            mma16816(d[0][ng][nt], A0.x, A1.x, A0.y, A1.y, bv.x, bv.y);  // Hh*Bh
            mma16816(d[0][ng][nt], A0.x, A1.x, A0.y, A1.y, bv.z, bv.w);  // Hh*Bl
            mma16816(d[0][ng][nt], A0.z, A1.z, A0.w, A1.w, bv.x, bv.y);  // Hl*Bh
            mma16816(d[1][ng][nt], A2.x, A3.x, A2.y, A3.y, bv.x, bv.y);
            mma16816(d[1][ng][nt], A2.x, A3.x, A2.y, A3.y, bv.z, bv.w);
            mma16816(d[1][ng][nt], A2.z, A3.z, A2.w, A3.w, bv.x, bv.y);
        }
    }
}

// ---------------------------------------------------------------------------
// Fused point-transformer. Block = 4 points (64 cols), 128 threads, 4 warps.
// ---------------------------------------------------------------------------
// dynamic smem layout (bytes)
#define SM_ATT2 0                        // uint4 [64][36] = 36864
#define SM_ATTF 36864                    // float [128][66] = 33792
#define SM_FSH  (36864 + 33792)          // float [4][128]  = 2048
#define SM_KC   (SM_FSH + 2048)          // float4 [64]     = 1024
#define SM_QC   (SM_KC + 1024)           // float4 [4]
#define SM_SMP  (SM_QC + 64)             // float [2][64]
#define SM_SMS  (SM_SMP + 512)
#define SM_SMI  (SM_SMS + 512)
#define SM_TOTAL (SM_SMI + 256)

__global__ __launch_bounds__(128, 3) void pt_kernel(
    const float* __restrict__ features,
    const float* __restrict__ phi_w,  const float* __restrict__ phi_b,
    const float* __restrict__ psi_w,  const float* __restrict__ psi_b,
    const float* __restrict__ g1_b,   const float* __restrict__ g2_b,
    const float* __restrict__ s1_w,   const float* __restrict__ s1_b,
    const float* __restrict__ s2_w,   const float* __restrict__ s2_b,
    const float* __restrict__ alpha_w, const float* __restrict__ alpha_b,
    float* __restrict__ out)
{
    extern __shared__ __align__(16) char sm[];
    uint4*  att2v = (uint4*)(sm + SM_ATT2);
    ushort* att2u = (ushort*)(sm + SM_ATT2);       // row stride 288 ushorts
    float (*att_f)[66] = (float(*)[66])(sm + SM_ATTF);
    float (*fsh)[NC]   = (float(*)[NC])(sm + SM_FSH);
    float4* kc         = (float4*)(sm + SM_KC);
    float4* qc         = (float4*)(sm + SM_QC);
    float (*smp)[64]   = (float(*)[64])(sm + SM_SMP);
    float (*sms)[64]   = (float(*)[64])(sm + SM_SMS);
    float* sminv       = (float*)(sm + SM_SMI);

    const int t    = threadIdx.x;
    const int c    = t & 63;
    const int cg   = t >> 6;
    const int pn0  = blockIdx.x * 4;
    const int b    = pn0 >> 12;
    const int n0_  = pn0 & (NP - 1);
    const int base = b * NP + n0_;

    // ---- loads ----
#pragma unroll
    for (int p = 0; p < 4; ++p)
        fsh[p][t] = features[(size_t)(base + p) * NC + t];
    if (t < 64) {
        int p  = t >> 4;
        int id = g_knn[(size_t)(base + p) * KN + (t & 15)];
        kc[t]  = g_c4[b * NP + id];
    }
    if (t < 4) qc[t] = g_c4[base + t];
    __syncthreads();

    // ---- xi = phi(features): thread handles channels 2c,2c+1, points 2cg,2cg+1 ----
    const int ch0 = 2 * c, ch1 = 2 * c + 1;
    float x00 = phi_b[ch0], x01 = x00;
    float x10 = phi_b[ch1], x11 = x10;
    {
        const float4* wa = (const float4*)(phi_w + (size_t)ch0 * NC);
        const float4* wb = (const float4*)(phi_w + (size_t)ch1 * NC);
        const float4* f0 = (const float4*)fsh[cg * 2 + 0];
        const float4* f1 = (const float4*)fsh[cg * 2 + 1];
#pragma unroll 4
        for (int i4 = 0; i4 < NC / 4; ++i4) {
            float4 a = wa[i4], bb = wb[i4], v0 = f0[i4], v1 = f1[i4];
            x00 = fmaf(a.x, v0.x, x00); x00 = fmaf(a.y, v0.y, x00);
            x00 = fmaf(a.z, v0.z, x00); x00 = fmaf(a.w, v0.w, x00);
            x01 = fmaf(a.x, v1.x, x01); x01 = fmaf(a.y, v1.y, x01);
            x01 = fmaf(a.z, v1.z, x01); x01 = fmaf(a.w, v1.w, x01);
            x10 = fmaf(bb.x, v0.x, x10); x10 = fmaf(bb.y, v0.y, x10);
            x10 = fmaf(bb.z, v0.z, x10); x10 = fmaf(bb.w, v0.w, x10);
            x11 = fmaf(bb.x, v1.x, x11); x11 = fmaf(bb.y, v1.y, x11);
            x11 = fmaf(bb.z, v1.z, x11); x11 = fmaf(bb.w, v1.w, x11);
        }
    }

    // ---- att0 = xi - psi(kc) + pos, split hi/lo into interleaved att2 ----
    {
        const float p00 = psi_w[ch0 * 3], p01 = psi_w[ch0 * 3 + 1], p02 = psi_w[ch0 * 3 + 2], p0b = psi_b[ch0];
        const float p10 = psi_w[ch1 * 3], p11 = psi_w[ch1 * 3 + 1], p12 = psi_w[ch1 * 3 + 2], p1b = psi_b[ch1];
        const float sa0 = s2_w[ch0 * 3], sa1 = s2_w[ch0 * 3 + 1], sa2 = s2_w[ch0 * 3 + 2], sab = s2_b[ch0];
        const float sb0 = s2_w[ch1 * 3], sb1 = s2_w[ch1 * 3 + 1], sb2 = s2_w[ch1 * 3 + 2], sbb = s2_b[ch1];
        const float w00 = s1_w[0], w01 = s1_w[1], w02 = s1_w[2];
        const float w10 = s1_w[3], w11 = s1_w[4], w12 = s1_w[5];
        const float w20 = s1_w[6], w21 = s1_w[7], w22 = s1_w[8];
        const float b0s = s1_b[0], b1s = s1_b[1], b2s = s1_b[2];
        // position of channel pair (ch0 even, ch1 = ch0+1) in interleaved layout
        const int ksq = ch0 >> 4;
        const int iq  = ch0 & 15;                              // even
        const int pq  = ((iq >> 1) & 3) * 4 + ((iq >> 3) << 1);
        const int hbase = (ksq * 4 + (pq >> 2)) * 8 + (pq & 3); // even -> uint aligned
#pragma unroll
        for (int jj = 0; jj < 32; ++jj) {
            int col = cg * 32 + jj;
            float4 cc = kc[col];
            float4 qv = qc[col >> 4];
            float rx = qv.x - cc.x, ry = qv.y - cc.y, rz = qv.z - cc.z;
            float h0 = fmaxf(w00 * rx + w01 * ry + w02 * rz + b0s, 0.0f);
            float h1 = fmaxf(w10 * rx + w11 * ry + w12 * rz + b1s, 0.0f);
            float h2 = fmaxf(w20 * rx + w21 * ry + w22 * rz + b2s, 0.0f);
            float pos0 = sa0 * h0 + sa1 * h1 + sa2 * h2 + sab;
            float pos1 = sb0 * h0 + sb1 * h1 + sb2 * h2 + sbb;
            float xj0  = p00 * cc.x + p01 * cc.y + p02 * cc.z + p0b;
            float xj1  = p10 * cc.x + p11 * cc.y + p12 * cc.z + p1b;
            float v0 = ((jj & 16) ? x01 : x00) - xj0 + pos0;
            float v1 = ((jj & 16) ? x11 : x10) - xj1 + pos1;
            __nv_bfloat16 vh0 = __float2bfloat16(v0);
            __nv_bfloat16 vh1 = __float2bfloat16(v1);
            __nv_bfloat16 vl0 = __float2bfloat16(v0 - __bfloat162float(vh0));
            __nv_bfloat16 vl1 = __float2bfloat16(v1 - __bfloat162float(vh1));
            int idx = col * 288 + hbase;
            *(uint*)&att2u[idx]     = (uint)__bfloat16_as_ushort(vh0) | ((uint)__bfloat16_as_ushort(vh1) << 16);
            *(uint*)&att2u[idx + 4] = (uint)__bfloat16_as_ushort(vl0) | ((uint)__bfloat16_as_ushort(vl1) << 16);
        }
    }
    __syncthreads();

    const int wid = t >> 5, lane = t & 31;
    const int gid = lane >> 2, tig = lane & 3;
    const int M0  = wid * 32;

    float d[2][2][4][4];

    // ================= gamma layer 1 =================
    gamma_mma(g_w1i, g1_b, att2v, M0, gid, tig, d);
    __syncthreads();   // everyone done reading att2
#pragma unroll
    for (int mt = 0; mt < 2; ++mt)
#pragma unroll
    for (int ng = 0; ng < 2; ++ng)
#pragma unroll
    for (int nt = 0; nt < 4; ++nt)
#pragma unroll
    for (int e = 0; e < 4; ++e) {
        float v = fmaxf(d[mt][ng][nt][e], 0.0f);
        int n    = ng * 32 + nt * 8 + 2 * tig + (e & 1);
        int mrow = M0 + mt * 16 + gid + 8 * (e >> 1);
        int ks2 = mrow >> 4, i2 = mrow & 15;
        int p2 = ((i2 >> 1) & 3) * 4 + (i2 & 1) + ((i2 >> 3) << 1);
        int idx = n * 288 + (ks2 * 4 + (p2 >> 2)) * 8 + (p2 & 3);
        __nv_bfloat16 h = __float2bfloat16(v);
        att2u[idx]     = __bfloat16_as_ushort(h);
        att2u[idx + 4] = __bfloat16_as_ushort(__float2bfloat16(v - __bfloat162float(h)));
    }
    __syncthreads();

    // ================= gamma layer 2 (fp32 out to att_f) =================
    gamma_mma(g_w2i, g2_b, att2v, M0, gid, tig, d);
#pragma unroll
    for (int mt = 0; mt < 2; ++mt)
#pragma unroll
    for (int ng = 0; ng < 2; ++ng)
#pragma unroll
    for (int nt = 0; nt < 4; ++nt) {
        int m = M0 + mt * 16 + gid;
        int n = ng * 32 + nt * 8 + 2 * tig;
        *(float2*)&att_f[m][n]     = make_float2(d[mt][ng][nt][0], d[mt][ng][nt][1]);
        *(float2*)&att_f[m + 8][n] = make_float2(d[mt][ng][nt][2], d[mt][ng][nt][3]);
    }
    __syncthreads();

    // ---- softmax over channels (rows), per column ----
    {
        int col = t & 63, h = t >> 6;
        float m = -3.4e38f;
#pragma unroll 8
        for (int i = h * 64; i < h * 64 + 64; ++i) m = fmaxf(m, att_f[i][col]);
        smp[h][col] = m;
        __syncthreads();
        m = fmaxf(smp[0][col], smp[1][col]);
        float s = 0.0f;
#pragma unroll 4
        for (int i = h * 64; i < h * 64 + 64; ++i) {
            float e = expf(att_f[i][col] - m);
            att_f[i][col] = e;
            s += e;
        }
        sms[h][col] = s;
        __syncthreads();
        if (t < 64) sminv[col] = 1.0f / (sms[0][col] + sms[1][col]);
        __syncthreads();
    }

    // ---- epilogue: out = sum_k softmax * (alpha(kc) + pos) ----
    {
        const int oa = c, ob = c + 64;
        const float aa0 = alpha_w[oa * 3], aa1 = alpha_w[oa * 3 + 1], aa2 = alpha_w[oa * 3 + 2], aab = alpha_b[oa];
        const float ab0 = alpha_w[ob * 3], ab1 = alpha_w[ob * 3 + 1], ab2 = alpha_w[ob * 3 + 2], abb = alpha_b[ob];
        const float s2a0 = s2_w[oa * 3], s2a1 = s2_w[oa * 3 + 1], s2a2 = s2_w[oa * 3 + 2], s2ab = s2_b[oa];
        const float s2b0 = s2_w[ob * 3], s2b1 = s2_w[ob * 3 + 1], s2b2 = s2_w[ob * 3 + 2], s2bb = s2_b[ob];
        const float w00 = s1_w[0], w01 = s1_w[1], w02 = s1_w[2];
        const float w10 = s1_w[3], w11 = s1_w[4], w12 = s1_w[5];
        const float w20 = s1_w[6], w21 = s1_w[7], w22 = s1_w[8];
        const float b0s = s1_b[0], b1s = s1_b[1], b2s = s1_b[2];

        float o0a = 0.0f, o1a = 0.0f, o0b = 0.0f, o1b = 0.0f;
#pragma unroll
        for (int jj = 0; jj < 32; ++jj) {
            int col = cg * 32 + jj;
            float4 cc = kc[col];
            float4 qv = qc[col >> 4];
            float rx = qv.x - cc.x, ry = qv.y - cc.y, rz = qv.z - cc.z;
            float h0 = fmaxf(w00 * rx + w01 * ry + w02 * rz + b0s, 0.0f);
            float h1 = fmaxf(w10 * rx + w11 * ry + w12 * rz + b1s, 0.0f);
            float h2 = fmaxf(w20 * rx + w21 * ry + w22 * rz + b2s, 0.0f);
            float posa = s2a0 * h0 + s2a1 * h1 + s2a2 * h2 + s2ab;
            float posb = s2b0 * h0 + s2b1 * h1 + s2b2 * h2 + s2bb;
            float va = aa0 * cc.x + aa1 * cc.y + aa2 * cc.z + aab + posa;
            float vb = ab0 * cc.x + ab1 * cc.y + ab2 * cc.z + abb + posb;
            float iv = sminv[col];
            float ea = att_f[oa][col] * iv;
            float eb = att_f[ob][col] * iv;
            if (jj < 16) { o0a += ea * va; o0b += eb * vb; }
            else         { o1a += ea * va; o1b += eb * vb; }
        }
        int p0 = cg * 2;
        out[(size_t)(base + p0) * NC + oa]     = o0a;
        out[(size_t)(base + p0) * NC + ob]     = o0b;
        out[(size_t)(base + p0 + 1) * NC + oa] = o1a;
        out[(size_t)(base + p0 + 1) * NC + ob] = o1b;
    }
}

// ---------------------------------------------------------------------------
extern "C" void kernel_launch(void* const* d_in, const int* in_sizes, int n_in,
                              void* d_out, int out_size)
{
    const float* coords   = (const float*)d_in[0];
    const float* features = (const float*)d_in[1];
    const float* phi_w    = (const float*)d_in[2];
    const float* phi_b    = (const float*)d_in[3];
    const float* psi_w    = (const float*)d_in[4];
    const float* psi_b    = (const float*)d_in[5];
    const float* g1_w     = (const float*)d_in[6];
    const float* g1_b     = (const float*)d_in[7];
    const float* g2_w     = (const float*)d_in[8];
    const float* g2_b     = (const float*)d_in[9];
    const float* s1_w     = (const float*)d_in[10];
    const float* s1_b     = (const float*)d_in[11];
    const float* s2_w     = (const float*)d_in[12];
    const float* s2_b     = (const float*)d_in[13];
    const float* alpha_w  = (const float*)d_in[14];
    const float* alpha_b  = (const float*)d_in[15];
    float* out = (float*)d_out;

    cudaFuncSetAttribute(pt_kernel, cudaFuncAttributeMaxDynamicSharedMemorySize, SM_TOTAL);

    prep_kernel<<<(NB * NP + 255) / 256, 256>>>(coords);
    split_kernel<<<(NC * NC + 255) / 256, 256>>>(g1_w, g2_w);
    knn_kernel<<<NB * NP * 32 / 256, 256>>>();
    pt_kernel<<<NB * NP / 4, 128, SM_TOTAL>>>(features,
                                              phi_w, phi_b, psi_w, psi_b,
                                              g1_b, g2_b,
                                              s1_w, s1_b, s2_w, s2_b,
                                              alpha_w, alpha_b, out);
}

// round 6
// speedup vs baseline: 2.7171x; 1.0083x over previous
#include <cuda_runtime.h>
#include <cuda_bf16.h>

#define NB 4
#define NP 4096
#define NC 128
#define KN 16
#define FULLM 0xFFFFFFFFu

typedef unsigned int uint;
typedef unsigned short ushort;

// scratch (no allocations allowed)
__device__ int    g_knn[NB * NP * KN];
__device__ float4 g_c4[NB * NP];
// interleaved split weights: per (m, ks, tig) one uint4 = {H01, H23, L01, L23}
__device__ uint4 g_w1i[NC * 32];
__device__ uint4 g_w2i[NC * 32];

// perm16: k%16 -> position so each mma fragment's 4 halves are contiguous
// p = ((i>>1)&3)*4 + (i&1) + ((i>>3)<<1)

// ---------------------------------------------------------------------------
__global__ void prep_kernel(const float* __restrict__ coords)
{
    int i = blockIdx.x * blockDim.x + threadIdx.x;
    if (i < NB * NP) {
        float x = coords[3 * i + 0], y = coords[3 * i + 1], z = coords[3 * i + 2];
        g_c4[i] = make_float4(x, y, z, x * x + y * y + z * z);
    }
}

// ---------------------------------------------------------------------------
__global__ void split_kernel(const float* __restrict__ g1w, const float* __restrict__ g2w)
{
    int i = blockIdx.x * blockDim.x + threadIdx.x;
    if (i >= NC * NC) return;
    int m = i >> 7, k = i & 127;
    int ks = k >> 4, ii = k & 15;
    int p = ((ii >> 1) & 3) * 4 + (ii & 1) + ((ii >> 3) << 1);
    int idx = (m * 32 + ks * 4 + (p >> 2)) * 8 + (p & 3);
    ushort* w1 = (ushort*)g_w1i;
    ushort* w2 = (ushort*)g_w2i;
    float x = g1w[i];
    __nv_bfloat16 h = __float2bfloat16(x);
    w1[idx]     = __bfloat16_as_ushort(h);
    w1[idx + 4] = __bfloat16_as_ushort(__float2bfloat16(x - __bfloat162float(h)));
    x = g2w[i];
    h = __float2bfloat16(x);
    w2[idx]     = __bfloat16_as_ushort(h);
    w2[idx + 4] = __bfloat16_as_ushort(__float2bfloat16(x - __bfloat162float(h)));
}

// ---------------------------------------------------------------------------
// kNN: one WARP per query (unchanged; passing since round 2)
// ---------------------------------------------------------------------------
__global__ __launch_bounds__(256) void knn_kernel()
{
    const int gw   = (blockIdx.x * blockDim.x + threadIdx.x) >> 5;
    const int lane = threadIdx.x & 31;
    const int b    = gw >> 12;
    const int q    = gw & (NP - 1);

    const float4* cb = g_c4 + b * NP;
    const float4  qc = cb[q];

    float lv  = 3.4e38f;
    int   li  = 0;
    float tau = 3.4e38f;

    for (int t = 0; t < NP / 32; ++t) {
        const int j = t * 32 + lane;
        float4 c = __ldg(cb + j);
        float dot = qc.x * c.x + qc.y * c.y + qc.z * c.z;
        float d2  = __fsub_rn(__fadd_rn(qc.w, c.w), __fmul_rn(2.0f, dot));

        unsigned m = __ballot_sync(FULLM, d2 < tau);
        while (m) {
            int src = __ffs(m) - 1; m &= m - 1;
            float v  = __shfl_sync(FULLM, d2, src);
            int   vi = t * 32 + src;
            if (v < tau) {
                unsigned le = __ballot_sync(FULLM, lv <= v) & 0xFFFFu;
                int pos = __popc(le);
                float upv = __shfl_up_sync(FULLM, lv, 1);
                int   upi = __shfl_up_sync(FULLM, li, 1);
                if (lane == pos)      { lv = v;   li = vi;  }
                else if (lane > pos)  { lv = upv; li = upi; }
                tau = __shfl_sync(FULLM, lv, 15);
            }
        }
    }
    if (lane < KN) g_knn[((size_t)b * NP + q) * KN + lane] = li;
}

// ---------------------------------------------------------------------------
__device__ __forceinline__ void mma16816(float (&d)[4], uint a0, uint a1, uint a2, uint a3,
                                         uint b0, uint b1)
{
    asm volatile(
        "mma.sync.aligned.m16n8k16.row.col.f32.bf16.bf16.f32 "
        "{%0,%1,%2,%3}, {%4,%5,%6,%7}, {%8,%9}, {%0,%1,%2,%3};"
        : "+f"(d[0]), "+f"(d[1]), "+f"(d[2]), "+f"(d[3])
        : "r"(a0), "r"(a1), "r"(a2), "r"(a3), "r"(b0), "r"(b1));
}

// One gamma layer, full 32 rows x 64 cols for this warp, 3-term bf16 split.
#define ATT2_STRIDE 36   // uint4 per col row; 576B = 64 mod 128 -> conflict-free

__device__ __forceinline__ void gamma_mma(
    const uint4* __restrict__ W, const float* __restrict__ bias,
    const uint4* __restrict__ att2v, int M0, int gid, int tig,
    float d[2][2][4][4])
{
#pragma unroll
    for (int mt = 0; mt < 2; ++mt) {
        float b0 = bias[M0 + mt * 16 + gid];
        float b1 = bias[M0 + mt * 16 + gid + 8];
#pragma unroll
        for (int ng = 0; ng < 2; ++ng)
#pragma unroll
        for (int nt = 0; nt < 4; ++nt) {
            d[mt][ng][nt][0] = b0; d[mt][ng][nt][1] = b0;
            d[mt][ng][nt][2] = b1; d[mt][ng][nt][3] = b1;
        }
    }
#pragma unroll
    for (int ks = 0; ks < 8; ++ks) {
        const int wo = ks * 4 + tig;
        uint4 A0 = W[(M0 + gid) * 32 + wo];
        uint4 A1 = W[(M0 + gid + 8) * 32 + wo];
        uint4 A2 = W[(M0 + 16 + gid) * 32 + wo];
        uint4 A3 = W[(M0 + 16 + gid + 8) * 32 + wo];
#pragma unroll
        for (int ng = 0; ng < 2; ++ng)
#pragma unroll
        for (int nt = 0; nt < 4; ++nt) {
            int n = ng * 32 + nt * 8 + gid;
            uint4 bv = att2v[n * ATT2_STRIDE + wo];
            mma16816(d[0][ng][nt], A0.x, A1.x, A0.y, A1.y, bv.x, bv.y);  // Hh*Bh
            mma16816(d[0][ng][nt], A0.x, A1.x, A0.y, A1.y, bv.z, bv.w);  // Hh*Bl
            mma16816(d[0][ng][nt], A0.z, A1.z, A0.w, A1.w, bv.x, bv.y);  // Hl*Bh
            mma16816(d[1][ng][nt], A2.x, A3.x, A2.y, A3.y, bv.x, bv.y);
            mma16816(d[1][ng][nt], A2.x, A3.x, A2.y, A3.y, bv.z, bv.w);
            mma16816(d[1][ng][nt], A2.z, A3.z, A2.w, A3.w, bv.x, bv.y);
        }
    }
}

// ---------------------------------------------------------------------------
// Fused point-transformer. Block = 4 points (64 cols), 128 threads, 4 warps.
// att_f ALIASES att2 (dead after layer-2 mma) -> smem 41.3KB -> 4 CTAs/SM.
// ---------------------------------------------------------------------------
// dynamic smem layout (bytes)
#define SM_ATT2 0                        // uint4 [64][36] = 36864; aliased by att_f (33792)
#define SM_FSH  36864                    // float [4][128]  = 2048
#define SM_KC   (SM_FSH + 2048)          // float4 [64]     = 1024
#define SM_QC   (SM_KC + 1024)           // float4 [4]
#define SM_SMP  (SM_QC + 64)             // float [2][64]
#define SM_SMS  (SM_SMP + 512)
#define SM_SMI  (SM_SMS + 512)
#define SM_TOTAL (SM_SMI + 256)

__global__ __launch_bounds__(128, 4) void pt_kernel(
    const float* __restrict__ features,
    const float* __restrict__ phi_w,  const float* __restrict__ phi_b,
    const float* __restrict__ psi_w,  const float* __restrict__ psi_b,
    const float* __restrict__ g1_b,   const float* __restrict__ g2_b,
    const float* __restrict__ s1_w,   const float* __restrict__ s1_b,
    const float* __restrict__ s2_w,   const float* __restrict__ s2_b,
    const float* __restrict__ alpha_w, const float* __restrict__ alpha_b,
    float* __restrict__ out)
{
    extern __shared__ __align__(16) char sm[];
    uint4*  att2v = (uint4*)(sm + SM_ATT2);
    ushort* att2u = (ushort*)(sm + SM_ATT2);       // row stride 288 ushorts
    float (*att_f)[66] = (float(*)[66])(sm + SM_ATT2);   // alias (att2 dead by then)
    float (*fsh)[NC]   = (float(*)[NC])(sm + SM_FSH);
    float4* kc         = (float4*)(sm + SM_KC);
    float4* qc         = (float4*)(sm + SM_QC);
    float (*smp)[64]   = (float(*)[64])(sm + SM_SMP);
    float (*sms)[64]   = (float(*)[64])(sm + SM_SMS);
    float* sminv       = (float*)(sm + SM_SMI);

    const int t    = threadIdx.x;
    const int c    = t & 63;
    const int cg   = t >> 6;
    const int pn0  = blockIdx.x * 4;
    const int b    = pn0 >> 12;
    const int n0_  = pn0 & (NP - 1);
    const int base = b * NP + n0_;

    // ---- loads ----
#pragma unroll
    for (int p = 0; p < 4; ++p)
        fsh[p][t] = features[(size_t)(base + p) * NC + t];
    if (t < 64) {
        int p  = t >> 4;
        int id = g_knn[(size_t)(base + p) * KN + (t & 15)];
        kc[t]  = g_c4[b * NP + id];
    }
    if (t < 4) qc[t] = g_c4[base + t];
    __syncthreads();

    // ---- xi = phi(features): thread handles channels 2c,2c+1, points 2cg,2cg+1 ----
    const int ch0 = 2 * c, ch1 = 2 * c + 1;
    float x00 = phi_b[ch0], x01 = x00;
    float x10 = phi_b[ch1], x11 = x10;
    {
        const float4* wa = (const float4*)(phi_w + (size_t)ch0 * NC);
        const float4* wb = (const float4*)(phi_w + (size_t)ch1 * NC);
        const float4* f0 = (const float4*)fsh[cg * 2 + 0];
        const float4* f1 = (const float4*)fsh[cg * 2 + 1];
#pragma unroll 4
        for (int i4 = 0; i4 < NC / 4; ++i4) {
            float4 a = wa[i4], bb = wb[i4], v0 = f0[i4], v1 = f1[i4];
            x00 = fmaf(a.x, v0.x, x00); x00 = fmaf(a.y, v0.y, x00);
            x00 = fmaf(a.z, v0.z, x00); x00 = fmaf(a.w, v0.w, x00);
            x01 = fmaf(a.x, v1.x, x01); x01 = fmaf(a.y, v1.y, x01);
            x01 = fmaf(a.z, v1.z, x01); x01 = fmaf(a.w, v1.w, x01);
            x10 = fmaf(bb.x, v0.x, x10); x10 = fmaf(bb.y, v0.y, x10);
            x10 = fmaf(bb.z, v0.z, x10); x10 = fmaf(bb.w, v0.w, x10);
            x11 = fmaf(bb.x, v1.x, x11); x11 = fmaf(bb.y, v1.y, x11);
            x11 = fmaf(bb.w, v1.w, x11); x11 = fmaf(bb.z, v1.z, x11);
        }
    }

    // ---- att0 = xi - psi(kc) + pos, split hi/lo into interleaved att2 ----
    {
        const float p00 = psi_w[ch0 * 3], p01 = psi_w[ch0 * 3 + 1], p02 = psi_w[ch0 * 3 + 2], p0b = psi_b[ch0];
        const float p10 = psi_w[ch1 * 3], p11 = psi_w[ch1 * 3 + 1], p12 = psi_w[ch1 * 3 + 2], p1b = psi_b[ch1];
        const float sa0 = s2_w[ch0 * 3], sa1 = s2_w[ch0 * 3 + 1], sa2 = s2_w[ch0 * 3 + 2], sab = s2_b[ch0];
        const float sb0 = s2_w[ch1 * 3], sb1 = s2_w[ch1 * 3 + 1], sb2 = s2_w[ch1 * 3 + 2], sbb = s2_b[ch1];
        const float w00 = s1_w[0], w01 = s1_w[1], w02 = s1_w[2];
        const float w10 = s1_w[3], w11 = s1_w[4], w12 = s1_w[5];
        const float w20 = s1_w[6], w21 = s1_w[7], w22 = s1_w[8];
        const float b0s = s1_b[0], b1s = s1_b[1], b2s = s1_b[2];
        const int ksq = ch0 >> 4;
        const int iq  = ch0 & 15;                              // even
        const int pq  = ((iq >> 1) & 3) * 4 + ((iq >> 3) << 1);
        const int hbase = (ksq * 4 + (pq >> 2)) * 8 + (pq & 3);
#pragma unroll
        for (int jj = 0; jj < 32; ++jj) {
            int col = cg * 32 + jj;
            float4 cc = kc[col];
            float4 qv = qc[col >> 4];
            float rx = qv.x - cc.x, ry = qv.y - cc.y, rz = qv.z - cc.z;
            float h0 = fmaxf(w00 * rx + w01 * ry + w02 * rz + b0s, 0.0f);
            float h1 = fmaxf(w10 * rx + w11 * ry + w12 * rz + b1s, 0.0f);
            float h2 = fmaxf(w20 * rx + w21 * ry + w22 * rz + b2s, 0.0f);
            float pos0 = sa0 * h0 + sa1 * h1 + sa2 * h2 + sab;
            float pos1 = sb0 * h0 + sb1 * h1 + sb2 * h2 + sbb;
            float xj0  = p00 * cc.x + p01 * cc.y + p02 * cc.z + p0b;
            float xj1  = p10 * cc.x + p11 * cc.y + p12 * cc.z + p1b;
            float v0 = ((jj & 16) ? x01 : x00) - xj0 + pos0;
            float v1 = ((jj & 16) ? x11 : x10) - xj1 + pos1;
            __nv_bfloat16 vh0 = __float2bfloat16(v0);
            __nv_bfloat16 vh1 = __float2bfloat16(v1);
            __nv_bfloat16 vl0 = __float2bfloat16(v0 - __bfloat162float(vh0));
            __nv_bfloat16 vl1 = __float2bfloat16(v1 - __bfloat162float(vh1));
            int idx = col * 288 + hbase;
            *(uint*)&att2u[idx]     = (uint)__bfloat16_as_ushort(vh0) | ((uint)__bfloat16_as_ushort(vh1) << 16);
            *(uint*)&att2u[idx + 4] = (uint)__bfloat16_as_ushort(vl0) | ((uint)__bfloat16_as_ushort(vl1) << 16);
        }
    }
    __syncthreads();

    const int wid = t >> 5, lane = t & 31;
    const int gid = lane >> 2, tig = lane & 3;
    const int M0  = wid * 32;

    float d[2][2][4][4];

    // ================= gamma layer 1 =================
    gamma_mma(g_w1i, g1_b, att2v, M0, gid, tig, d);
    __syncthreads();   // everyone done reading att2
#pragma unroll
    for (int mt = 0; mt < 2; ++mt)
#pragma unroll
    for (int ng = 0; ng < 2; ++ng)
#pragma unroll
    for (int nt = 0; nt < 4; ++nt)
#pragma unroll
    for (int e = 0; e < 4; ++e) {
        float v = fmaxf(d[mt][ng][nt][e], 0.0f);
        int n    = ng * 32 + nt * 8 + 2 * tig + (e & 1);
        int mrow = M0 + mt * 16 + gid + 8 * (e >> 1);
        int ks2 = mrow >> 4, i2 = mrow & 15;
        int p2 = ((i2 >> 1) & 3) * 4 + (i2 & 1) + ((i2 >> 3) << 1);
        int idx = n * 288 + (ks2 * 4 + (p2 >> 2)) * 8 + (p2 & 3);
        __nv_bfloat16 h = __float2bfloat16(v);
        att2u[idx]     = __bfloat16_as_ushort(h);
        att2u[idx + 4] = __bfloat16_as_ushort(__float2bfloat16(v - __bfloat162float(h)));
    }
    __syncthreads();

    // ================= gamma layer 2 (fp32 out to att_f, aliasing att2) =====
    gamma_mma(g_w2i, g2_b, att2v, M0, gid, tig, d);
    __syncthreads();   // att2 fully read by ALL warps before aliased overwrite
#pragma unroll
    for (int mt = 0; mt < 2; ++mt)
#pragma unroll
    for (int ng = 0; ng < 2; ++ng)
#pragma unroll
    for (int nt = 0; nt < 4; ++nt) {
        int m = M0 + mt * 16 + gid;
        int n = ng * 32 + nt * 8 + 2 * tig;
        *(float2*)&att_f[m][n]     = make_float2(d[mt][ng][nt][0], d[mt][ng][nt][1]);
        *(float2*)&att_f[m + 8][n] = make_float2(d[mt][ng][nt][2], d[mt][ng][nt][3]);
    }
    __syncthreads();

    // ---- softmax over channels (rows), per column ----
    {
        int col = t & 63, h = t >> 6;
        float m = -3.4e38f;
#pragma unroll 8
        for (int i = h * 64; i < h * 64 + 64; ++i) m = fmaxf(m, att_f[i][col]);
        smp[h][col] = m;
        __syncthreads();
        m = fmaxf(smp[0][col], smp[1][col]);
        float s = 0.0f;
#pragma unroll 4
        for (int i = h * 64; i < h * 64 + 64; ++i) {
            float e = __expf(att_f[i][col] - m);
            att_f[i][col] = e;
            s += e;
        }
        sms[h][col] = s;
        __syncthreads();
        if (t < 64) sminv[col] = 1.0f / (sms[0][col] + sms[1][col]);
        __syncthreads();
    }

    // ---- epilogue: out = sum_k softmax * (alpha(kc) + pos) ----
    {
        const int oa = c, ob = c + 64;
        const float aa0 = alpha_w[oa * 3], aa1 = alpha_w[oa * 3 + 1], aa2 = alpha_w[oa * 3 + 2], aab = alpha_b[oa];
        const float ab0 = alpha_w[ob * 3], ab1 = alpha_w[ob * 3 + 1], ab2 = alpha_w[ob * 3 + 2], abb = alpha_b[ob];
        const float s2a0 = s2_w[oa * 3], s2a1 = s2_w[oa * 3 + 1], s2a2 = s2_w[oa * 3 + 2], s2ab = s2_b[oa];
        const float s2b0 = s2_w[ob * 3], s2b1 = s2_w[ob * 3 + 1], s2b2 = s2_w[ob * 3 + 2], s2bb = s2_b[ob];
        const float w00 = s1_w[0], w01 = s1_w[1], w02 = s1_w[2];
        const float w10 = s1_w[3], w11 = s1_w[4], w12 = s1_w[5];
        const float w20 = s1_w[6], w21 = s1_w[7], w22 = s1_w[8];
        const float b0s = s1_b[0], b1s = s1_b[1], b2s = s1_b[2];

        float o0a = 0.0f, o1a = 0.0f, o0b = 0.0f, o1b = 0.0f;
#pragma unroll
        for (int jj = 0; jj < 32; ++jj) {
            int col = cg * 32 + jj;
            float4 cc = kc[col];
            float4 qv = qc[col >> 4];
            float rx = qv.x - cc.x, ry = qv.y - cc.y, rz = qv.z - cc.z;
            float h0 = fmaxf(w00 * rx + w01 * ry + w02 * rz + b0s, 0.0f);
            float h1 = fmaxf(w10 * rx + w11 * ry + w12 * rz + b1s, 0.0f);
            float h2 = fmaxf(w20 * rx + w21 * ry + w22 * rz + b2s, 0.0f);
            float posa = s2a0 * h0 + s2a1 * h1 + s2a2 * h2 + s2ab;
            float posb = s2b0 * h0 + s2b1 * h1 + s2b2 * h2 + s2bb;
            float va = aa0 * cc.x + aa1 * cc.y + aa2 * cc.z + aab + posa;
            float vb = ab0 * cc.x + ab1 * cc.y + ab2 * cc.z + abb + posb;
            float iv = sminv[col];
            float ea = att_f[oa][col] * iv;
            float eb = att_f[ob][col] * iv;
            if (jj < 16) { o0a += ea * va; o0b += eb * vb; }
            else         { o1a += ea * va; o1b += eb * vb; }
        }
        int p0 = cg * 2;
        out[(size_t)(base + p0) * NC + oa]     = o0a;
        out[(size_t)(base + p0) * NC + ob]     = o0b;
        out[(size_t)(base + p0 + 1) * NC + oa] = o1a;
        out[(size_t)(base + p0 + 1) * NC + ob] = o1b;
    }
}

// ---------------------------------------------------------------------------
extern "C" void kernel_launch(void* const* d_in, const int* in_sizes, int n_in,
                              void* d_out, int out_size)
{
    const float* coords   = (const float*)d_in[0];
    const float* features = (const float*)d_in[1];
    const float* phi_w    = (const float*)d_in[2];
    const float* phi_b    = (const float*)d_in[3];
    const float* psi_w    = (const float*)d_in[4];
    const float* psi_b    = (const float*)d_in[5];
    const float* g1_w     = (const float*)d_in[6];
    const float* g1_b     = (const float*)d_in[7];
    const float* g2_w     = (const float*)d_in[8];
    const float* g2_b     = (const float*)d_in[9];
    const float* s1_w     = (const float*)d_in[10];
    const float* s1_b     = (const float*)d_in[11];
    const float* s2_w     = (const float*)d_in[12];
    const float* s2_b     = (const float*)d_in[13];
    const float* alpha_w  = (const float*)d_in[14];
    const float* alpha_b  = (const float*)d_in[15];
    float* out = (float*)d_out;

    cudaFuncSetAttribute(pt_kernel, cudaFuncAttributeMaxDynamicSharedMemorySize, SM_TOTAL);

    prep_kernel<<<(NB * NP + 255) / 256, 256>>>(coords);
    split_kernel<<<(NC * NC + 255) / 256, 256>>>(g1_w, g2_w);
    knn_kernel<<<NB * NP * 32 / 256, 256>>>();
    pt_kernel<<<NB * NP / 4, 128, SM_TOTAL>>>(features,
                                              phi_w, phi_b, psi_w, psi_b,
                                              g1_b, g2_b,
                                              s1_w, s1_b, s2_w, s2_b,
                                              alpha_w, alpha_b, out);
}

// round 7
// speedup vs baseline: 3.4864x; 1.2831x over previous
#include <cuda_runtime.h>
#include <cuda_bf16.h>

#define NB 4
#define NP 4096
#define NC 128
#define KN 16
#define FULLM 0xFFFFFFFFu

typedef unsigned int uint;
typedef unsigned short ushort;

// scratch (no allocations allowed)
__device__ int    g_knn[NB * NP * KN];
__device__ float4 g_c4[NB * NP];
__device__ float  g_xi[NB * NP * NC];          // phi(features), precomputed
// interleaved split weights: per (m, ks, tig) one uint4 = {H01, H23, L01, L23}
__device__ uint4 g_w1i[NC * 32];
__device__ uint4 g_w2i[NC * 32];
__device__ uint4 g_wpi[NC * 32];               // phi_w split

// perm16: k%16 -> position so each mma fragment's 4 halves are contiguous
// p = ((i>>1)&3)*4 + (i&1) + ((i>>3)<<1)

// ---------------------------------------------------------------------------
__global__ void prep_kernel(const float* __restrict__ coords)
{
    int i = blockIdx.x * blockDim.x + threadIdx.x;
    if (i < NB * NP) {
        float x = coords[3 * i + 0], y = coords[3 * i + 1], z = coords[3 * i + 2];
        g_c4[i] = make_float4(x, y, z, x * x + y * y + z * z);
    }
}

// ---------------------------------------------------------------------------
__global__ void split_kernel(const float* __restrict__ g1w, const float* __restrict__ g2w,
                             const float* __restrict__ pw)
{
    int i = blockIdx.x * blockDim.x + threadIdx.x;
    if (i >= NC * NC) return;
    int m = i >> 7, k = i & 127;
    int ks = k >> 4, ii = k & 15;
    int p = ((ii >> 1) & 3) * 4 + (ii & 1) + ((ii >> 3) << 1);
    int idx = (m * 32 + ks * 4 + (p >> 2)) * 8 + (p & 3);
    ushort* w1 = (ushort*)g_w1i;
    ushort* w2 = (ushort*)g_w2i;
    ushort* wp = (ushort*)g_wpi;
    float x; __nv_bfloat16 h;
    x = g1w[i]; h = __float2bfloat16(x);
    w1[idx] = __bfloat16_as_ushort(h);
    w1[idx + 4] = __bfloat16_as_ushort(__float2bfloat16(x - __bfloat162float(h)));
    x = g2w[i]; h = __float2bfloat16(x);
    w2[idx] = __bfloat16_as_ushort(h);
    w2[idx + 4] = __bfloat16_as_ushort(__float2bfloat16(x - __bfloat162float(h)));
    x = pw[i]; h = __float2bfloat16(x);
    wp[idx] = __bfloat16_as_ushort(h);
    wp[idx + 4] = __bfloat16_as_ushort(__float2bfloat16(x - __bfloat162float(h)));
}

// ---------------------------------------------------------------------------
// kNN: one WARP per query (unchanged; passing since round 2)
// ---------------------------------------------------------------------------
__global__ __launch_bounds__(256) void knn_kernel()
{
    const int gw   = (blockIdx.x * blockDim.x + threadIdx.x) >> 5;
    const int lane = threadIdx.x & 31;
    const int b    = gw >> 12;
    const int q    = gw & (NP - 1);

    const float4* cb = g_c4 + b * NP;
    const float4  qc = cb[q];

    float lv  = 3.4e38f;
    int   li  = 0;
    float tau = 3.4e38f;

    for (int t = 0; t < NP / 32; ++t) {
        const int j = t * 32 + lane;
        float4 c = __ldg(cb + j);
        float dot = qc.x * c.x + qc.y * c.y + qc.z * c.z;
        float d2  = __fsub_rn(__fadd_rn(qc.w, c.w), __fmul_rn(2.0f, dot));

        unsigned m = __ballot_sync(FULLM, d2 < tau);
        while (m) {
            int src = __ffs(m) - 1; m &= m - 1;
            float v  = __shfl_sync(FULLM, d2, src);
            int   vi = t * 32 + src;
            if (v < tau) {
                unsigned le = __ballot_sync(FULLM, lv <= v) & 0xFFFFu;
                int pos = __popc(le);
                float upv = __shfl_up_sync(FULLM, lv, 1);
                int   upi = __shfl_up_sync(FULLM, li, 1);
                if (lane == pos)      { lv = v;   li = vi;  }
                else if (lane > pos)  { lv = upv; li = upi; }
                tau = __shfl_sync(FULLM, lv, 15);
            }
        }
    }
    if (lane < KN) g_knn[((size_t)b * NP + q) * KN + lane] = li;
}

// ---------------------------------------------------------------------------
__device__ __forceinline__ void mma16816(float (&d)[4], uint a0, uint a1, uint a2, uint a3,
                                         uint b0, uint b1)
{
    asm volatile(
        "mma.sync.aligned.m16n8k16.row.col.f32.bf16.bf16.f32 "
        "{%0,%1,%2,%3}, {%4,%5,%6,%7}, {%8,%9}, {%0,%1,%2,%3};"
        : "+f"(d[0]), "+f"(d[1]), "+f"(d[2]), "+f"(d[3])
        : "r"(a0), "r"(a1), "r"(a2), "r"(a3), "r"(b0), "r"(b1));
}

// One layer, full 32 rows x 64 cols for this warp, 3-term bf16 split.
#define ATT2_STRIDE 36   // uint4 per col row; 576B = 64 mod 128 -> conflict-free

__device__ __forceinline__ void gamma_mma(
    const uint4* __restrict__ W, const float* __restrict__ bias,
    const uint4* __restrict__ att2v, int M0, int gid, int tig,
    float d[2][2][4][4])
{
#pragma unroll
    for (int mt = 0; mt < 2; ++mt) {
        float b0 = bias[M0 + mt * 16 + gid];
        float b1 = bias[M0 + mt * 16 + gid + 8];
#pragma unroll
        for (int ng = 0; ng < 2; ++ng)
#pragma unroll
        for (int nt = 0; nt < 4; ++nt) {
            d[mt][ng][nt][0] = b0; d[mt][ng][nt][1] = b0;
            d[mt][ng][nt][2] = b1; d[mt][ng][nt][3] = b1;
        }
    }
#pragma unroll
    for (int ks = 0; ks < 8; ++ks) {
        const int wo = ks * 4 + tig;
        uint4 A0 = W[(M0 + gid) * 32 + wo];
        uint4 A1 = W[(M0 + gid + 8) * 32 + wo];
        uint4 A2 = W[(M0 + 16 + gid) * 32 + wo];
        uint4 A3 = W[(M0 + 16 + gid + 8) * 32 + wo];
#pragma unroll
        for (int ng = 0; ng < 2; ++ng)
#pragma unroll
        for (int nt = 0; nt < 4; ++nt) {
            int n = ng * 32 + nt * 8 + gid;
            uint4 bv = att2v[n * ATT2_STRIDE + wo];
            mma16816(d[0][ng][nt], A0.x, A1.x, A0.y, A1.y, bv.x, bv.y);  // Hh*Bh
            mma16816(d[0][ng][nt], A0.x, A1.x, A0.y, A1.y, bv.z, bv.w);  // Hh*Bl
            mma16816(d[0][ng][nt], A0.z, A1.z, A0.w, A1.w, bv.x, bv.y);  // Hl*Bh
            mma16816(d[1][ng][nt], A2.x, A3.x, A2.y, A3.y, bv.x, bv.y);
            mma16816(d[1][ng][nt], A2.x, A3.x, A2.y, A3.y, bv.z, bv.w);
            mma16816(d[1][ng][nt], A2.z, A3.z, A2.w, A3.w, bv.x, bv.y);
        }
    }
}

// ---------------------------------------------------------------------------
// phi_kernel: xi = phi(features) for all points, via MMA. Block = 64 points.
// ---------------------------------------------------------------------------
__global__ __launch_bounds__(128) void phi_kernel(const float* __restrict__ features,
                                                  const float* __restrict__ phi_b)
{
    __shared__ __align__(16) char fsm[64 * 576];
    uint4*  f2v = (uint4*)fsm;
    ushort* f2u = (ushort*)fsm;

    const int t     = threadIdx.x;
    const int pbase = blockIdx.x * 64;
    const float4* fv = (const float4*)(features + (size_t)pbase * NC);

    // stage features (64 pts x 128 ch) split hi/lo into interleaved layout
#pragma unroll
    for (int it = 0; it < 16; ++it) {
        int li  = it * 128 + t;
        int col = li >> 5;
        int c4  = li & 31;
        float4 v = fv[li];
        int ch = c4 * 4;
        int ks = ch >> 4, ii = ch & 15;                       // ii in {0,4,8,12}
        int p  = ((ii >> 1) & 3) * 4 + ((ii >> 3) << 1);
        int idx = col * 288 + (ks * 4 + (p >> 2)) * 8 + (p & 3);
        __nv_bfloat16 h0 = __float2bfloat16(v.x), h1 = __float2bfloat16(v.y);
        __nv_bfloat16 h2 = __float2bfloat16(v.z), h3 = __float2bfloat16(v.w);
        __nv_bfloat16 l0 = __float2bfloat16(v.x - __bfloat162float(h0));
        __nv_bfloat16 l1 = __float2bfloat16(v.y - __bfloat162float(h1));
        __nv_bfloat16 l2 = __float2bfloat16(v.z - __bfloat162float(h2));
        __nv_bfloat16 l3 = __float2bfloat16(v.w - __bfloat162float(h3));
        *(uint*)&f2u[idx]      = (uint)__bfloat16_as_ushort(h0) | ((uint)__bfloat16_as_ushort(h1) << 16);
        *(uint*)&f2u[idx + 4]  = (uint)__bfloat16_as_ushort(l0) | ((uint)__bfloat16_as_ushort(l1) << 16);
        *(uint*)&f2u[idx + 8]  = (uint)__bfloat16_as_ushort(h2) | ((uint)__bfloat16_as_ushort(h3) << 16);
        *(uint*)&f2u[idx + 12] = (uint)__bfloat16_as_ushort(l2) | ((uint)__bfloat16_as_ushort(l3) << 16);
    }
    __syncthreads();

    const int wid = t >> 5, lane = t & 31;
    const int gid = lane >> 2, tig = lane & 3;
    const int M0  = wid * 32;

    float d[2][2][4][4];
    gamma_mma(g_wpi, phi_b, f2v, M0, gid, tig, d);

#pragma unroll
    for (int mt = 0; mt < 2; ++mt)
#pragma unroll
    for (int ng = 0; ng < 2; ++ng)
#pragma unroll
    for (int nt = 0; nt < 4; ++nt) {
        int m = M0 + mt * 16 + gid;
        int n = ng * 32 + nt * 8 + 2 * tig;
        size_t r0 = (size_t)(pbase + n) * NC;
        g_xi[r0 + m]            = d[mt][ng][nt][0];
        g_xi[r0 + NC + m]       = d[mt][ng][nt][1];
        g_xi[r0 + m + 8]        = d[mt][ng][nt][2];
        g_xi[r0 + NC + m + 8]   = d[mt][ng][nt][3];
    }
}

// ---------------------------------------------------------------------------
// Fused point-transformer. Block = 4 points (64 cols), 128 threads, 4 warps.
// att_f ALIASES att2 (dead after layer-2 mma) -> smem 41.3KB -> 4 CTAs/SM.
// ---------------------------------------------------------------------------
// dynamic smem layout (bytes)
#define SM_ATT2 0                        // uint4 [64][36] = 36864; aliased by att_f (33792)
#define SM_XI   36864                    // float [4][128]  = 2048
#define SM_KC   (SM_XI + 2048)           // float4 [64]     = 1024
#define SM_QC   (SM_KC + 1024)           // float4 [4]
#define SM_SMP  (SM_QC + 64)             // float [2][64]
#define SM_SMS  (SM_SMP + 512)
#define SM_SMI  (SM_SMS + 512)
#define SM_TOTAL (SM_SMI + 256)

__global__ __launch_bounds__(128, 4) void pt_kernel(
    const float* __restrict__ psi_w,  const float* __restrict__ psi_b,
    const float* __restrict__ g1_b,   const float* __restrict__ g2_b,
    const float* __restrict__ s1_w,   const float* __restrict__ s1_b,
    const float* __restrict__ s2_w,   const float* __restrict__ s2_b,
    const float* __restrict__ alpha_w, const float* __restrict__ alpha_b,
    float* __restrict__ out)
{
    extern __shared__ __align__(16) char sm[];
    uint4*  att2v = (uint4*)(sm + SM_ATT2);
    ushort* att2u = (ushort*)(sm + SM_ATT2);            // row stride 288 ushorts
    float (*att_f)[66] = (float(*)[66])(sm + SM_ATT2);  // alias (att2 dead by then)
    float (*xish)[NC]  = (float(*)[NC])(sm + SM_XI);
    float4* kc         = (float4*)(sm + SM_KC);
    float4* qc         = (float4*)(sm + SM_QC);
    float (*smp)[64]   = (float(*)[64])(sm + SM_SMP);
    float (*sms)[64]   = (float(*)[64])(sm + SM_SMS);
    float* sminv       = (float*)(sm + SM_SMI);

    const int t    = threadIdx.x;
    const int c    = t & 63;
    const int cg   = t >> 6;
    const int pn0  = blockIdx.x * 4;
    const int b    = pn0 >> 12;
    const int n0_  = pn0 & (NP - 1);
    const int base = b * NP + n0_;

    // ---- loads (xi coalesced: one float4 per thread) ----
    {
        int p = t >> 5, f4 = t & 31;
        ((float4*)xish[p])[f4] = ((const float4*)(g_xi + (size_t)(base + p) * NC))[f4];
    }
    if (t < 64) {
        int p  = t >> 4;
        int id = g_knn[(size_t)(base + p) * KN + (t & 15)];
        kc[t]  = g_c4[b * NP + id];
    }
    if (t < 4) qc[t] = g_c4[base + t];
    __syncthreads();

    // ---- att0 = xi - psi(kc) + pos, split hi/lo into interleaved att2 ----
    const int ch0 = 2 * c, ch1 = 2 * c + 1;
    {
        const float x00 = xish[cg * 2 + 0][ch0], x01 = xish[cg * 2 + 1][ch0];
        const float x10 = xish[cg * 2 + 0][ch1], x11 = xish[cg * 2 + 1][ch1];
        const float p00 = psi_w[ch0 * 3], p01 = psi_w[ch0 * 3 + 1], p02 = psi_w[ch0 * 3 + 2], p0b = psi_b[ch0];
        const float p10 = psi_w[ch1 * 3], p11 = psi_w[ch1 * 3 + 1], p12 = psi_w[ch1 * 3 + 2], p1b = psi_b[ch1];
        const float sa0 = s2_w[ch0 * 3], sa1 = s2_w[ch0 * 3 + 1], sa2 = s2_w[ch0 * 3 + 2], sab = s2_b[ch0];
        const float sb0 = s2_w[ch1 * 3], sb1 = s2_w[ch1 * 3 + 1], sb2 = s2_w[ch1 * 3 + 2], sbb = s2_b[ch1];
        const float w00 = s1_w[0], w01 = s1_w[1], w02 = s1_w[2];
        const float w10 = s1_w[3], w11 = s1_w[4], w12 = s1_w[5];
        const float w20 = s1_w[6], w21 = s1_w[7], w22 = s1_w[8];
        const float b0s = s1_b[0], b1s = s1_b[1], b2s = s1_b[2];
        const int ksq = ch0 >> 4;
        const int iq  = ch0 & 15;                              // even
        const int pq  = ((iq >> 1) & 3) * 4 + ((iq >> 3) << 1);
        const int hbase = (ksq * 4 + (pq >> 2)) * 8 + (pq & 3);
#pragma unroll
        for (int jj = 0; jj < 32; ++jj) {
            int col = cg * 32 + jj;
            float4 cc = kc[col];
            float4 qv = qc[col >> 4];
            float rx = qv.x - cc.x, ry = qv.y - cc.y, rz = qv.z - cc.z;
            float h0 = fmaxf(w00 * rx + w01 * ry + w02 * rz + b0s, 0.0f);
            float h1 = fmaxf(w10 * rx + w11 * ry + w12 * rz + b1s, 0.0f);
            float h2 = fmaxf(w20 * rx + w21 * ry + w22 * rz + b2s, 0.0f);
            float pos0 = sa0 * h0 + sa1 * h1 + sa2 * h2 + sab;
            float pos1 = sb0 * h0 + sb1 * h1 + sb2 * h2 + sbb;
            float xj0  = p00 * cc.x + p01 * cc.y + p02 * cc.z + p0b;
            float xj1  = p10 * cc.x + p11 * cc.y + p12 * cc.z + p1b;
            float v0 = ((jj & 16) ? x01 : x00) - xj0 + pos0;
            float v1 = ((jj & 16) ? x11 : x10) - xj1 + pos1;
            __nv_bfloat16 vh0 = __float2bfloat16(v0);
            __nv_bfloat16 vh1 = __float2bfloat16(v1);
            __nv_bfloat16 vl0 = __float2bfloat16(v0 - __bfloat162float(vh0));
            __nv_bfloat16 vl1 = __float2bfloat16(v1 - __bfloat162float(vh1));
            int idx = col * 288 + hbase;
            *(uint*)&att2u[idx]     = (uint)__bfloat16_as_ushort(vh0) | ((uint)__bfloat16_as_ushort(vh1) << 16);
            *(uint*)&att2u[idx + 4] = (uint)__bfloat16_as_ushort(vl0) | ((uint)__bfloat16_as_ushort(vl1) << 16);
        }
    }
    __syncthreads();

    const int wid = t >> 5, lane = t & 31;
    const int gid = lane >> 2, tig = lane & 3;
    const int M0  = wid * 32;

    float d[2][2][4][4];

    // ================= gamma layer 1 =================
    gamma_mma(g_w1i, g1_b, att2v, M0, gid, tig, d);
    __syncthreads();   // everyone done reading att2
#pragma unroll
    for (int mt = 0; mt < 2; ++mt)
#pragma unroll
    for (int ng = 0; ng < 2; ++ng)
#pragma unroll
    for (int nt = 0; nt < 4; ++nt)
#pragma unroll
    for (int e = 0; e < 4; ++e) {
        float v = fmaxf(d[mt][ng][nt][e], 0.0f);
        int n    = ng * 32 + nt * 8 + 2 * tig + (e & 1);
        int mrow = M0 + mt * 16 + gid + 8 * (e >> 1);
        int ks2 = mrow >> 4, i2 = mrow & 15;
        int p2 = ((i2 >> 1) & 3) * 4 + (i2 & 1) + ((i2 >> 3) << 1);
        int idx = n * 288 + (ks2 * 4 + (p2 >> 2)) * 8 + (p2 & 3);
        __nv_bfloat16 h = __float2bfloat16(v);
        att2u[idx]     = __bfloat16_as_ushort(h);
        att2u[idx + 4] = __bfloat16_as_ushort(__float2bfloat16(v - __bfloat162float(h)));
    }
    __syncthreads();

    // ================= gamma layer 2 (fp32 out to att_f, aliasing att2) =====
    gamma_mma(g_w2i, g2_b, att2v, M0, gid, tig, d);
    __syncthreads();   // att2 fully read by ALL warps before aliased overwrite
#pragma unroll
    for (int mt = 0; mt < 2; ++mt)
#pragma unroll
    for (int ng = 0; ng < 2; ++ng)
#pragma unroll
    for (int nt = 0; nt < 4; ++nt) {
        int m = M0 + mt * 16 + gid;
        int n = ng * 32 + nt * 8 + 2 * tig;
        *(float2*)&att_f[m][n]     = make_float2(d[mt][ng][nt][0], d[mt][ng][nt][1]);
        *(float2*)&att_f[m + 8][n] = make_float2(d[mt][ng][nt][2], d[mt][ng][nt][3]);
    }
    __syncthreads();

    // ---- softmax over channels (rows), per column ----
    {
        int col = t & 63, h = t >> 6;
        float m = -3.4e38f;
#pragma unroll 8
        for (int i = h * 64; i < h * 64 + 64; ++i) m = fmaxf(m, att_f[i][col]);
        smp[h][col] = m;
        __syncthreads();
        m = fmaxf(smp[0][col], smp[1][col]);
        float s = 0.0f;
#pragma unroll 4
        for (int i = h * 64; i < h * 64 + 64; ++i) {
            float e = __expf(att_f[i][col] - m);
            att_f[i][col] = e;
            s += e;
        }
        sms[h][col] = s;
        __syncthreads();
        if (t < 64) sminv[col] = 1.0f / (sms[0][col] + sms[1][col]);
        __syncthreads();
    }

    // ---- epilogue: out = sum_k softmax * (alpha(kc) + pos) ----
    {
        const int oa = c, ob = c + 64;
        const float aa0 = alpha_w[oa * 3], aa1 = alpha_w[oa * 3 + 1], aa2 = alpha_w[oa * 3 + 2], aab = alpha_b[oa];
        const float ab0 = alpha_w[ob * 3], ab1 = alpha_w[ob * 3 + 1], ab2 = alpha_w[ob * 3 + 2], abb = alpha_b[ob];
        const float s2a0 = s2_w[oa * 3], s2a1 = s2_w[oa * 3 + 1], s2a2 = s2_w[oa * 3 + 2], s2ab = s2_b[oa];
        const float s2b0 = s2_w[ob * 3], s2b1 = s2_w[ob * 3 + 1], s2b2 = s2_w[ob * 3 + 2], s2bb = s2_b[ob];
        const float w00 = s1_w[0], w01 = s1_w[1], w02 = s1_w[2];
        const float w10 = s1_w[3], w11 = s1_w[4], w12 = s1_w[5];
        const float w20 = s1_w[6], w21 = s1_w[7], w22 = s1_w[8];
        const float b0s = s1_b[0], b1s = s1_b[1], b2s = s1_b[2];

        float o0a = 0.0f, o1a = 0.0f, o0b = 0.0f, o1b = 0.0f;
#pragma unroll
        for (int jj = 0; jj < 32; ++jj) {
            int col = cg * 32 + jj;
            float4 cc = kc[col];
            float4 qv = qc[col >> 4];
            float rx = qv.x - cc.x, ry = qv.y - cc.y, rz = qv.z - cc.z;
            float h0 = fmaxf(w00 * rx + w01 * ry + w02 * rz + b0s, 0.0f);
            float h1 = fmaxf(w10 * rx + w11 * ry + w12 * rz + b1s, 0.0f);
            float h2 = fmaxf(w20 * rx + w21 * ry + w22 * rz + b2s, 0.0f);
            float posa = s2a0 * h0 + s2a1 * h1 + s2a2 * h2 + s2ab;
            float posb = s2b0 * h0 + s2b1 * h1 + s2b2 * h2 + s2bb;
            float va = aa0 * cc.x + aa1 * cc.y + aa2 * cc.z + aab + posa;
            float vb = ab0 * cc.x + ab1 * cc.y + ab2 * cc.z + abb + posb;
            float iv = sminv[col];
            float ea = att_f[oa][col] * iv;
            float eb = att_f[ob][col] * iv;
            if (jj < 16) { o0a += ea * va; o0b += eb * vb; }
            else         { o1a += ea * va; o1b += eb * vb; }
        }
        int p0 = cg * 2;
        out[(size_t)(base + p0) * NC + oa]     = o0a;
        out[(size_t)(base + p0) * NC + ob]     = o0b;
        out[(size_t)(base + p0 + 1) * NC + oa] = o1a;
        out[(size_t)(base + p0 + 1) * NC + ob] = o1b;
    }
}

// ---------------------------------------------------------------------------
extern "C" void kernel_launch(void* const* d_in, const int* in_sizes, int n_in,
                              void* d_out, int out_size)
{
    const float* coords   = (const float*)d_in[0];
    const float* features = (const float*)d_in[1];
    const float* phi_w    = (const float*)d_in[2];
    const float* phi_b    = (const float*)d_in[3];
    const float* psi_w    = (const float*)d_in[4];
    const float* psi_b    = (const float*)d_in[5];
    const float* g1_w     = (const float*)d_in[6];
    const float* g1_b     = (const float*)d_in[7];
    const float* g2_w     = (const float*)d_in[8];
    const float* g2_b     = (const float*)d_in[9];
    const float* s1_w     = (const float*)d_in[10];
    const float* s1_b     = (const float*)d_in[11];
    const float* s2_w     = (const float*)d_in[12];
    const float* s2_b     = (const float*)d_in[13];
    const float* alpha_w  = (const float*)d_in[14];
    const float* alpha_b  = (const float*)d_in[15];
    float* out = (float*)d_out;

    cudaFuncSetAttribute(pt_kernel, cudaFuncAttributeMaxDynamicSharedMemorySize, SM_TOTAL);

    prep_kernel<<<(NB * NP + 255) / 256, 256>>>(coords);
    split_kernel<<<(NC * NC + 255) / 256, 256>>>(g1_w, g2_w, phi_w);
    phi_kernel<<<NB * NP / 64, 128>>>(features, phi_b);
    knn_kernel<<<NB * NP * 32 / 256, 256>>>();
    pt_kernel<<<NB * NP / 4, 128, SM_TOTAL>>>(psi_w, psi_b,
                                              g1_b, g2_b,
                                              s1_w, s1_b, s2_w, s2_b,
                                              alpha_w, alpha_b, out);
}

// round 8
// speedup vs baseline: 4.9602x; 1.4228x over previous
#include <cuda_runtime.h>
#include <cuda_bf16.h>

#define NB 4
#define NP 4096
#define NC 128
#define KN 16
#define FULLM 0xFFFFFFFFu

typedef unsigned int uint;
typedef unsigned short ushort;

// scratch (no allocations allowed)
__device__ int    g_knn[NB * NP * KN];
__device__ float4 g_c4[NB * NP];
__device__ float  g_y[NB * NP * NC];           // Y = g1_w @ phi(features)
__device__ float  g_a7[NC * 8];                // A7 = g1_w @ W7 (+g1_b), padded to 8
__device__ float  g_zeros[NC];                 // zero bias (static zero-init)
// interleaved split weights: per (m, ks, tig) one uint4 = {H01, H23, L01, L23}
__device__ uint4 g_w1i[NC * 32];
__device__ uint4 g_w2i[NC * 32];
__device__ uint4 g_wpi[NC * 32];               // phi_w split

// ---------------------------------------------------------------------------
__global__ void prep_kernel(const float* __restrict__ coords)
{
    int i = blockIdx.x * blockDim.x + threadIdx.x;
    if (i < NB * NP) {
        float x = coords[3 * i + 0], y = coords[3 * i + 1], z = coords[3 * i + 2];
        g_c4[i] = make_float4(x, y, z, x * x + y * y + z * z);
    }
}

// ---------------------------------------------------------------------------
__global__ void split_kernel(const float* __restrict__ g1w, const float* __restrict__ g2w,
                             const float* __restrict__ pw)
{
    int i = blockIdx.x * blockDim.x + threadIdx.x;
    if (i >= NC * NC) return;
    int m = i >> 7, k = i & 127;
    int ks = k >> 4, ii = k & 15;
    int p = ((ii >> 1) & 3) * 4 + (ii & 1) + ((ii >> 3) << 1);
    int idx = (m * 32 + ks * 4 + (p >> 2)) * 8 + (p & 3);
    ushort* w1 = (ushort*)g_w1i;
    ushort* w2 = (ushort*)g_w2i;
    ushort* wp = (ushort*)g_wpi;
    float x; __nv_bfloat16 h;
    x = g1w[i]; h = __float2bfloat16(x);
    w1[idx] = __bfloat16_as_ushort(h);
    w1[idx + 4] = __bfloat16_as_ushort(__float2bfloat16(x - __bfloat162float(h)));
    x = g2w[i]; h = __float2bfloat16(x);
    w2[idx] = __bfloat16_as_ushort(h);
    w2[idx + 4] = __bfloat16_as_ushort(__float2bfloat16(x - __bfloat162float(h)));
    x = pw[i]; h = __float2bfloat16(x);
    wp[idx] = __bfloat16_as_ushort(h);
    wp[idx + 4] = __bfloat16_as_ushort(__float2bfloat16(x - __bfloat162float(h)));
}

// ---------------------------------------------------------------------------
// A7[ch][0:3] = -g1w@psi_w, [3:6] = g1w@s2_w, [6] = g1w@(s2_b - psi_b) + g1_b
// ---------------------------------------------------------------------------
__global__ void a7_kernel(const float* __restrict__ g1w, const float* __restrict__ g1b,
                          const float* __restrict__ psw, const float* __restrict__ psb,
                          const float* __restrict__ s2w, const float* __restrict__ s2b)
{
    int ch = threadIdx.x;
    float a0 = 0, a1 = 0, a2 = 0, a3 = 0, a4 = 0, a5 = 0, a6 = 0;
    for (int i = 0; i < NC; ++i) {
        float gv = g1w[ch * NC + i];
        a0 = fmaf(gv, -psw[i * 3 + 0], a0);
        a1 = fmaf(gv, -psw[i * 3 + 1], a1);
        a2 = fmaf(gv, -psw[i * 3 + 2], a2);
        a3 = fmaf(gv, s2w[i * 3 + 0], a3);
        a4 = fmaf(gv, s2w[i * 3 + 1], a4);
        a5 = fmaf(gv, s2w[i * 3 + 2], a5);
        a6 = fmaf(gv, s2b[i] - psb[i], a6);
    }
    g_a7[ch * 8 + 0] = a0; g_a7[ch * 8 + 1] = a1; g_a7[ch * 8 + 2] = a2;
    g_a7[ch * 8 + 3] = a3; g_a7[ch * 8 + 4] = a4; g_a7[ch * 8 + 5] = a5;
    g_a7[ch * 8 + 6] = a6 + g1b[ch];
    g_a7[ch * 8 + 7] = 0.0f;
}

// ---------------------------------------------------------------------------
// kNN: one WARP per query, 2 candidates per lane per step.
// a-half (indices t*64..+31) processed fully before b-half (+32..+63) so
// insertion order stays ascending-index (lax.top_k tie semantics).
// ---------------------------------------------------------------------------
__global__ __launch_bounds__(256) void knn_kernel()
{
    const int gw   = (blockIdx.x * blockDim.x + threadIdx.x) >> 5;
    const int lane = threadIdx.x & 31;
    const int b    = gw >> 12;
    const int q    = gw & (NP - 1);

    const float4* cb = g_c4 + b * NP;
    const float4  qc = cb[q];

    float lv  = 3.4e38f;
    int   li  = 0;
    float tau = 3.4e38f;

    for (int t = 0; t < NP / 64; ++t) {
        const int j0 = t * 64 + lane;
        float4 c1 = __ldg(cb + j0);
        float4 c2 = __ldg(cb + j0 + 32);
        float dota = qc.x * c1.x + qc.y * c1.y + qc.z * c1.z;
        float dotb = qc.x * c2.x + qc.y * c2.y + qc.z * c2.z;
        float d2a = __fsub_rn(__fadd_rn(qc.w, c1.w), __fmul_rn(2.0f, dota));
        float d2b = __fsub_rn(__fadd_rn(qc.w, c2.w), __fmul_rn(2.0f, dotb));

        unsigned m = __ballot_sync(FULLM, d2a < tau);
        while (m) {
            int src = __ffs(m) - 1; m &= m - 1;
            float v  = __shfl_sync(FULLM, d2a, src);
            int   vi = t * 64 + src;
            if (v < tau) {
                unsigned le = __ballot_sync(FULLM, lv <= v) & 0xFFFFu;
                int pos = __popc(le);
                float upv = __shfl_up_sync(FULLM, lv, 1);
                int   upi = __shfl_up_sync(FULLM, li, 1);
                if (lane == pos)      { lv = v;   li = vi;  }
                else if (lane > pos)  { lv = upv; li = upi; }
                tau = __shfl_sync(FULLM, lv, 15);
            }
        }
        m = __ballot_sync(FULLM, d2b < tau);
        while (m) {
            int src = __ffs(m) - 1; m &= m - 1;
            float v  = __shfl_sync(FULLM, d2b, src);
            int   vi = t * 64 + 32 + src;
            if (v < tau) {
                unsigned le = __ballot_sync(FULLM, lv <= v) & 0xFFFFu;
                int pos = __popc(le);
                float upv = __shfl_up_sync(FULLM, lv, 1);
                int   upi = __shfl_up_sync(FULLM, li, 1);
                if (lane == pos)      { lv = v;   li = vi;  }
                else if (lane > pos)  { lv = upv; li = upi; }
                tau = __shfl_sync(FULLM, lv, 15);
            }
        }
    }
    if (lane < KN) g_knn[((size_t)b * NP + q) * KN + lane] = li;
}

// ---------------------------------------------------------------------------
__device__ __forceinline__ void mma16816(float (&d)[4], uint a0, uint a1, uint a2, uint a3,
                                         uint b0, uint b1)
{
    asm volatile(
        "mma.sync.aligned.m16n8k16.row.col.f32.bf16.bf16.f32 "
        "{%0,%1,%2,%3}, {%4,%5,%6,%7}, {%8,%9}, {%0,%1,%2,%3};"
        : "+f"(d[0]), "+f"(d[1]), "+f"(d[2]), "+f"(d[3])
        : "r"(a0), "r"(a1), "r"(a2), "r"(a3), "r"(b0), "r"(b1));
}

#define ATT2_STRIDE 36   // uint4 per col row; 576B = 64 mod 128 -> conflict-free

__device__ __forceinline__ void gamma_mma(
    const uint4* __restrict__ W, const float* __restrict__ bias,
    const uint4* __restrict__ att2v, int M0, int gid, int tig,
    float d[2][2][4][4])
{
#pragma unroll
    for (int mt = 0; mt < 2; ++mt) {
        float b0 = bias[M0 + mt * 16 + gid];
        float b1 = bias[M0 + mt * 16 + gid + 8];
#pragma unroll
        for (int ng = 0; ng < 2; ++ng)
#pragma unroll
        for (int nt = 0; nt < 4; ++nt) {
            d[mt][ng][nt][0] = b0; d[mt][ng][nt][1] = b0;
            d[mt][ng][nt][2] = b1; d[mt][ng][nt][3] = b1;
        }
    }
#pragma unroll
    for (int ks = 0; ks < 8; ++ks) {
        const int wo = ks * 4 + tig;
        uint4 A0 = W[(M0 + gid) * 32 + wo];
        uint4 A1 = W[(M0 + gid + 8) * 32 + wo];
        uint4 A2 = W[(M0 + 16 + gid) * 32 + wo];
        uint4 A3 = W[(M0 + 16 + gid + 8) * 32 + wo];
#pragma unroll
        for (int ng = 0; ng < 2; ++ng)
#pragma unroll
        for (int nt = 0; nt < 4; ++nt) {
            int n = ng * 32 + nt * 8 + gid;
            uint4 bv = att2v[n * ATT2_STRIDE + wo];
            mma16816(d[0][ng][nt], A0.x, A1.x, A0.y, A1.y, bv.x, bv.y);  // Hh*Bh
            mma16816(d[0][ng][nt], A0.x, A1.x, A0.y, A1.y, bv.z, bv.w);  // Hh*Bl
            mma16816(d[0][ng][nt], A0.z, A1.z, A0.w, A1.w, bv.x, bv.y);  // Hl*Bh
            mma16816(d[1][ng][nt], A2.x, A3.x, A2.y, A3.y, bv.x, bv.y);
            mma16816(d[1][ng][nt], A2.x, A3.x, A2.y, A3.y, bv.z, bv.w);
            mma16816(d[1][ng][nt], A2.z, A3.z, A2.w, A3.w, bv.x, bv.y);
        }
    }
}

// ---------------------------------------------------------------------------
// phi_kernel: Y = g1_w @ (phi_w @ f + phi_b) for all points. Block = 64 pts.
// Stage 1: xi = phi(f) via MMA. Stage 2: Y = g1 @ xi via MMA (zero bias).
// ---------------------------------------------------------------------------
__global__ __launch_bounds__(128) void phi_kernel(const float* __restrict__ features,
                                                  const float* __restrict__ phi_b)
{
    __shared__ __align__(16) char fsm[64 * 576];
    uint4*  f2v = (uint4*)fsm;
    ushort* f2u = (ushort*)fsm;

    const int t     = threadIdx.x;
    const int pbase = blockIdx.x * 64;
    const float4* fv = (const float4*)(features + (size_t)pbase * NC);

    // stage features (64 pts x 128 ch) split hi/lo into interleaved layout
#pragma unroll
    for (int it = 0; it < 16; ++it) {
        int li  = it * 128 + t;
        int col = li >> 5;
        int c4  = li & 31;
        float4 v = fv[li];
        int ch = c4 * 4;
        int ks = ch >> 4, ii = ch & 15;                       // ii in {0,4,8,12}
        int p  = ((ii >> 1) & 3) * 4 + ((ii >> 3) << 1);
        int idx = col * 288 + (ks * 4 + (p >> 2)) * 8 + (p & 3);
        __nv_bfloat16 h0 = __float2bfloat16(v.x), h1 = __float2bfloat16(v.y);
        __nv_bfloat16 h2 = __float2bfloat16(v.z), h3 = __float2bfloat16(v.w);
        __nv_bfloat16 l0 = __float2bfloat16(v.x - __bfloat162float(h0));
        __nv_bfloat16 l1 = __float2bfloat16(v.y - __bfloat162float(h1));
        __nv_bfloat16 l2 = __float2bfloat16(v.z - __bfloat162float(h2));
        __nv_bfloat16 l3 = __float2bfloat16(v.w - __bfloat162float(h3));
        *(uint*)&f2u[idx]      = (uint)__bfloat16_as_ushort(h0) | ((uint)__bfloat16_as_ushort(h1) << 16);
        *(uint*)&f2u[idx + 4]  = (uint)__bfloat16_as_ushort(l0) | ((uint)__bfloat16_as_ushort(l1) << 16);
        *(uint*)&f2u[idx + 8]  = (uint)__bfloat16_as_ushort(h2) | ((uint)__bfloat16_as_ushort(h3) << 16);
        *(uint*)&f2u[idx + 12] = (uint)__bfloat16_as_ushort(l2) | ((uint)__bfloat16_as_ushort(l3) << 16);
    }
    __syncthreads();

    const int wid = t >> 5, lane = t & 31;
    const int gid = lane >> 2, tig = lane & 3;
    const int M0  = wid * 32;

    float d[2][2][4][4];
    gamma_mma(g_wpi, phi_b, f2v, M0, gid, tig, d);     // xi
    __syncthreads();   // all warps done reading staged features

    // scatter xi (split) back into f2 layout: [col=point][k=channel]
#pragma unroll
    for (int mt = 0; mt < 2; ++mt)
#pragma unroll
    for (int ng = 0; ng < 2; ++ng)
#pragma unroll
    for (int nt = 0; nt < 4; ++nt)
#pragma unroll
    for (int e = 0; e < 4; ++e) {
        float v = d[mt][ng][nt][e];
        int n    = ng * 32 + nt * 8 + 2 * tig + (e & 1);
        int mrow = M0 + mt * 16 + gid + 8 * (e >> 1);
        int ks2 = mrow >> 4, i2 = mrow & 15;
        int p2 = ((i2 >> 1) & 3) * 4 + (i2 & 1) + ((i2 >> 3) << 1);
        int idx = n * 288 + (ks2 * 4 + (p2 >> 2)) * 8 + (p2 & 3);
        __nv_bfloat16 h = __float2bfloat16(v);
        f2u[idx]     = __bfloat16_as_ushort(h);
        f2u[idx + 4] = __bfloat16_as_ushort(__float2bfloat16(v - __bfloat162float(h)));
    }
    __syncthreads();

    gamma_mma(g_w1i, g_zeros, f2v, M0, gid, tig, d);   // Y = g1 @ xi

#pragma unroll
    for (int mt = 0; mt < 2; ++mt)
#pragma unroll
    for (int ng = 0; ng < 2; ++ng)
#pragma unroll
    for (int nt = 0; nt < 4; ++nt) {
        int m = M0 + mt * 16 + gid;
        int n = ng * 32 + nt * 8 + 2 * tig;
        size_t r0 = (size_t)(pbase + n) * NC;
        g_y[r0 + m]            = d[mt][ng][nt][0];
        g_y[r0 + NC + m]       = d[mt][ng][nt][1];
        g_y[r0 + m + 8]        = d[mt][ng][nt][2];
        g_y[r0 + NC + m + 8]   = d[mt][ng][nt][3];
    }
}

// ---------------------------------------------------------------------------
// Fused point-transformer. Block = 4 points (64 cols), 128 threads, 4 warps.
// Layer 1 folded to 7-dim fp32 affine (A7.g + Y); layer 2 via MMA.
// ---------------------------------------------------------------------------
// dynamic smem layout (bytes)
#define SM_ATT2 0                        // uint4 [64][36] = 36864; aliased by att_f
#define SM_Y    36864                    // float [4][128]  = 2048
#define SM_G    (SM_Y + 2048)            // float [64][8]   = 2048
#define SM_KC   (SM_G + 2048)            // float4 [64]     = 1024
#define SM_QC   (SM_KC + 1024)           // float4 [4]
#define SM_SMP  (SM_QC + 64)             // float [2][64]
#define SM_SMS  (SM_SMP + 512)
#define SM_SMI  (SM_SMS + 512)
#define SM_TOTAL (SM_SMI + 256)

__global__ __launch_bounds__(128, 4) void pt_kernel(
    const float* __restrict__ g2_b,
    const float* __restrict__ s1_w,   const float* __restrict__ s1_b,
    const float* __restrict__ s2_w,   const float* __restrict__ s2_b,
    const float* __restrict__ alpha_w, const float* __restrict__ alpha_b,
    float* __restrict__ out)
{
    extern __shared__ __align__(16) char sm[];
    uint4*  att2v = (uint4*)(sm + SM_ATT2);
    ushort* att2u = (ushort*)(sm + SM_ATT2);            // row stride 288 ushorts
    float (*att_f)[66] = (float(*)[66])(sm + SM_ATT2);  // alias (att2 dead by then)
    float (*ysh)[NC]   = (float(*)[NC])(sm + SM_Y);
    float4* gsh        = (float4*)(sm + SM_G);          // [64][2] float4
    float4* kc         = (float4*)(sm + SM_KC);
    float4* qc         = (float4*)(sm + SM_QC);
    float (*smp)[64]   = (float(*)[64])(sm + SM_SMP);
    float (*sms)[64]   = (float(*)[64])(sm + SM_SMS);
    float* sminv       = (float*)(sm + SM_SMI);

    const int t    = threadIdx.x;
    const int c    = t & 63;
    const int cg   = t >> 6;
    const int pn0  = blockIdx.x * 4;
    const int b    = pn0 >> 12;
    const int n0_  = pn0 & (NP - 1);
    const int base = b * NP + n0_;

    // ---- loads (Y coalesced: one float4 per thread) ----
    {
        int p = t >> 5, f4 = t & 31;
        ((float4*)ysh[p])[f4] = ((const float4*)(g_y + (size_t)(base + p) * NC))[f4];
    }
    if (t < 64) {
        int p  = t >> 4;
        int id = g_knn[(size_t)(base + p) * KN + (t & 15)];
        kc[t]  = g_c4[b * NP + id];
    }
    if (t < 4) qc[t] = g_c4[base + t];
    __syncthreads();

    // ---- g[col] = [kc, h(col), 1, 0] computed once per column ----
    if (t < 64) {
        float4 cc = kc[t];
        float4 qv = qc[t >> 4];
        float rx = qv.x - cc.x, ry = qv.y - cc.y, rz = qv.z - cc.z;
        float h0 = fmaxf(s1_w[0] * rx + s1_w[1] * ry + s1_w[2] * rz + s1_b[0], 0.0f);
        float h1 = fmaxf(s1_w[3] * rx + s1_w[4] * ry + s1_w[5] * rz + s1_b[1], 0.0f);
        float h2 = fmaxf(s1_w[6] * rx + s1_w[7] * ry + s1_w[8] * rz + s1_b[2], 0.0f);
        gsh[t * 2]     = make_float4(cc.x, cc.y, cc.z, h0);
        gsh[t * 2 + 1] = make_float4(h1, h2, 1.0f, 0.0f);
    }
    __syncthreads();

    // ---- layer 1 (folded): l1 = relu(A7.g + Y), split into att2 ----
    const int ch0 = 2 * c, ch1 = 2 * c + 1;
    {
        const float4* a7v = (const float4*)g_a7;
        float4 a0l = a7v[ch0 * 2], a0h = a7v[ch0 * 2 + 1];
        float4 a1l = a7v[ch1 * 2], a1h = a7v[ch1 * 2 + 1];
        const float y00 = ysh[cg * 2 + 0][ch0], y01 = ysh[cg * 2 + 1][ch0];
        const float y10 = ysh[cg * 2 + 0][ch1], y11 = ysh[cg * 2 + 1][ch1];
        const int ksq = ch0 >> 4;
        const int iq  = ch0 & 15;                              // even
        const int pq  = ((iq >> 1) & 3) * 4 + ((iq >> 3) << 1);
        const int hbase = (ksq * 4 + (pq >> 2)) * 8 + (pq & 3);
#pragma unroll
        for (int jj = 0; jj < 32; ++jj) {
            int col = cg * 32 + jj;
            float4 gl = gsh[col * 2], gh = gsh[col * 2 + 1];
            float v0 = a0l.x * gl.x + a0l.y * gl.y + a0l.z * gl.z + a0l.w * gl.w
                     + a0h.x * gh.x + a0h.y * gh.y + a0h.z
                     + ((jj & 16) ? y01 : y00);
            float v1 = a1l.x * gl.x + a1l.y * gl.y + a1l.z * gl.z + a1l.w * gl.w
                     + a1h.x * gh.x + a1h.y * gh.y + a1h.z
                     + ((jj & 16) ? y11 : y10);
            v0 = fmaxf(v0, 0.0f);
            v1 = fmaxf(v1, 0.0f);
            __nv_bfloat16 vh0 = __float2bfloat16(v0);
            __nv_bfloat16 vh1 = __float2bfloat16(v1);
            __nv_bfloat16 vl0 = __float2bfloat16(v0 - __bfloat162float(vh0));
            __nv_bfloat16 vl1 = __float2bfloat16(v1 - __bfloat162float(vh1));
            int idx = col * 288 + hbase;
            *(uint*)&att2u[idx]     = (uint)__bfloat16_as_ushort(vh0) | ((uint)__bfloat16_as_ushort(vh1) << 16);
            *(uint*)&att2u[idx + 4] = (uint)__bfloat16_as_ushort(vl0) | ((uint)__bfloat16_as_ushort(vl1) << 16);
        }
    }
    __syncthreads();

    const int wid = t >> 5, lane = t & 31;
    const int gid = lane >> 2, tig = lane & 3;
    const int M0  = wid * 32;

    float d[2][2][4][4];

    // ================= gamma layer 2 (MMA; fp32 out to att_f alias) =========
    gamma_mma(g_w2i, g2_b, att2v, M0, gid, tig, d);
    __syncthreads();   // att2 fully read by ALL warps before aliased overwrite
#pragma unroll
    for (int mt = 0; mt < 2; ++mt)
#pragma unroll
    for (int ng = 0; ng < 2; ++ng)
#pragma unroll
    for (int nt = 0; nt < 4; ++nt) {
        int m = M0 + mt * 16 + gid;
        int n = ng * 32 + nt * 8 + 2 * tig;
        *(float2*)&att_f[m][n]     = make_float2(d[mt][ng][nt][0], d[mt][ng][nt][1]);
        *(float2*)&att_f[m + 8][n] = make_float2(d[mt][ng][nt][2], d[mt][ng][nt][3]);
    }
    __syncthreads();

    // ---- softmax over channels (rows), per column ----
    {
        int col = t & 63, h = t >> 6;
        float m = -3.4e38f;
#pragma unroll 8
        for (int i = h * 64; i < h * 64 + 64; ++i) m = fmaxf(m, att_f[i][col]);
        smp[h][col] = m;
        __syncthreads();
        m = fmaxf(smp[0][col], smp[1][col]);
        float s = 0.0f;
#pragma unroll 4
        for (int i = h * 64; i < h * 64 + 64; ++i) {
            float e = __expf(att_f[i][col] - m);
            att_f[i][col] = e;
            s += e;
        }
        sms[h][col] = s;
        __syncthreads();
        if (t < 64) sminv[col] = 1.0f / (sms[0][col] + sms[1][col]);
        __syncthreads();
    }

    // ---- epilogue: out = sum_k softmax * (V7.g) ----
    {
        const int oa = c, ob = c + 64;
        const float aa0 = alpha_w[oa * 3], aa1 = alpha_w[oa * 3 + 1], aa2 = alpha_w[oa * 3 + 2];
        const float ab0 = alpha_w[ob * 3], ab1 = alpha_w[ob * 3 + 1], ab2 = alpha_w[ob * 3 + 2];
        const float s2a0 = s2_w[oa * 3], s2a1 = s2_w[oa * 3 + 1], s2a2 = s2_w[oa * 3 + 2];
        const float s2b0 = s2_w[ob * 3], s2b1 = s2_w[ob * 3 + 1], s2b2 = s2_w[ob * 3 + 2];
        const float ca = alpha_b[oa] + s2_b[oa];
        const float cb = alpha_b[ob] + s2_b[ob];

        float o0a = 0.0f, o1a = 0.0f, o0b = 0.0f, o1b = 0.0f;
#pragma unroll
        for (int jj = 0; jj < 32; ++jj) {
            int col = cg * 32 + jj;
            float4 gl = gsh[col * 2], gh = gsh[col * 2 + 1];
            float va = aa0 * gl.x + aa1 * gl.y + aa2 * gl.z + s2a0 * gl.w
                     + s2a1 * gh.x + s2a2 * gh.y + ca;
            float vb = ab0 * gl.x + ab1 * gl.y + ab2 * gl.z + s2b0 * gl.w
                     + s2b1 * gh.x + s2b2 * gh.y + cb;
            float iv = sminv[col];
            float ea = att_f[oa][col] * iv;
            float eb = att_f[ob][col] * iv;
            if (jj < 16) { o0a += ea * va; o0b += eb * vb; }
            else         { o1a += ea * va; o1b += eb * vb; }
        }
        int p0 = cg * 2;
        out[(size_t)(base + p0) * NC + oa]     = o0a;
        out[(size_t)(base + p0) * NC + ob]     = o0b;
        out[(size_t)(base + p0 + 1) * NC + oa] = o1a;
        out[(size_t)(base + p0 + 1) * NC + ob] = o1b;
    }
}

// ---------------------------------------------------------------------------
extern "C" void kernel_launch(void* const* d_in, const int* in_sizes, int n_in,
                              void* d_out, int out_size)
{
    const float* coords   = (const float*)d_in[0];
    const float* features = (const float*)d_in[1];
    const float* phi_w    = (const float*)d_in[2];
    const float* phi_b    = (const float*)d_in[3];
    const float* psi_w    = (const float*)d_in[4];
    const float* psi_b    = (const float*)d_in[5];
    const float* g1_w     = (const float*)d_in[6];
    const float* g1_b     = (const float*)d_in[7];
    const float* g2_w     = (const float*)d_in[8];
    const float* g2_b     = (const float*)d_in[9];
    const float* s1_w     = (const float*)d_in[10];
    const float* s1_b     = (const float*)d_in[11];
    const float* s2_w     = (const float*)d_in[12];
    const float* s2_b     = (const float*)d_in[13];
    const float* alpha_w  = (const float*)d_in[14];
    const float* alpha_b  = (const float*)d_in[15];
    float* out = (float*)d_out;

    cudaFuncSetAttribute(pt_kernel, cudaFuncAttributeMaxDynamicSharedMemorySize, SM_TOTAL);

    prep_kernel<<<(NB * NP + 255) / 256, 256>>>(coords);
    split_kernel<<<(NC * NC + 255) / 256, 256>>>(g1_w, g2_w, phi_w);
    a7_kernel<<<1, NC>>>(g1_w, g1_b, psi_w, psi_b, s2_w, s2_b);
    phi_kernel<<<NB * NP / 64, 128>>>(features, phi_b);
    knn_kernel<<<NB * NP * 32 / 256, 256>>>();
    pt_kernel<<<NB * NP / 4, 128, SM_TOTAL>>>(g2_b,
                                              s1_w, s1_b, s2_w, s2_b,
                                              alpha_w, alpha_b, out);
}

// round 9
// speedup vs baseline: 5.0724x; 1.0226x over previous
#include <cuda_runtime.h>
#include <cuda_bf16.h>

#define NB 4
#define NP 4096
#define NC 128
#define KN 16
#define FULLM 0xFFFFFFFFu

typedef unsigned int uint;
typedef unsigned short ushort;

// scratch (no allocations allowed)
__device__ int    g_knn[NB * NP * KN];
__device__ float4 g_c4[NB * NP];
__device__ float  g_y[NB * NP * NC];           // Y = g1_w @ phi(features)
__device__ float  g_a7[NC * 8];                // A7 = g1_w @ W7 (+g1_b), padded to 8
__device__ float  g_zeros[NC];                 // zero bias (static zero-init)
// interleaved split weights: per (m, ks, tig) one uint4 = {H01, H23, L01, L23}
__device__ uint4 g_w1i[NC * 32];
__device__ uint4 g_w2i[NC * 32];
__device__ uint4 g_wpi[NC * 32];               // phi_w split

// ---------------------------------------------------------------------------
// setup: prep (blocks 0..63) + weight split (64..127) + a7 (128)
// ---------------------------------------------------------------------------
__global__ __launch_bounds__(256) void setup_kernel(
    const float* __restrict__ coords,
    const float* __restrict__ g1w, const float* __restrict__ g2w,
    const float* __restrict__ pw,
    const float* __restrict__ g1b,
    const float* __restrict__ psw, const float* __restrict__ psb,
    const float* __restrict__ s2w, const float* __restrict__ s2b)
{
    const int bk = blockIdx.x, t = threadIdx.x;
    if (bk < 64) {
        int i = bk * 256 + t;
        float x = coords[3 * i + 0], y = coords[3 * i + 1], z = coords[3 * i + 2];
        g_c4[i] = make_float4(x, y, z, x * x + y * y + z * z);
    } else if (bk < 128) {
        int i = (bk - 64) * 256 + t;
        int m = i >> 7, k = i & 127;
        int ks = k >> 4, ii = k & 15;
        int p = ((ii >> 1) & 3) * 4 + (ii & 1) + ((ii >> 3) << 1);
        int idx = (m * 32 + ks * 4 + (p >> 2)) * 8 + (p & 3);
        ushort* w1 = (ushort*)g_w1i;
        ushort* w2 = (ushort*)g_w2i;
        ushort* wp = (ushort*)g_wpi;
        float x; __nv_bfloat16 h;
        x = g1w[i]; h = __float2bfloat16(x);
        w1[idx] = __bfloat16_as_ushort(h);
        w1[idx + 4] = __bfloat16_as_ushort(__float2bfloat16(x - __bfloat162float(h)));
        x = g2w[i]; h = __float2bfloat16(x);
        w2[idx] = __bfloat16_as_ushort(h);
        w2[idx + 4] = __bfloat16_as_ushort(__float2bfloat16(x - __bfloat162float(h)));
        x = pw[i]; h = __float2bfloat16(x);
        wp[idx] = __bfloat16_as_ushort(h);
        wp[idx + 4] = __bfloat16_as_ushort(__float2bfloat16(x - __bfloat162float(h)));
    } else if (t < NC) {
        int ch = t;
        float a0 = 0, a1 = 0, a2 = 0, a3 = 0, a4 = 0, a5 = 0, a6 = 0;
        for (int i = 0; i < NC; ++i) {
            float gv = g1w[ch * NC + i];
            a0 = fmaf(gv, -psw[i * 3 + 0], a0);
            a1 = fmaf(gv, -psw[i * 3 + 1], a1);
            a2 = fmaf(gv, -psw[i * 3 + 2], a2);
            a3 = fmaf(gv, s2w[i * 3 + 0], a3);
            a4 = fmaf(gv, s2w[i * 3 + 1], a4);
            a5 = fmaf(gv, s2w[i * 3 + 2], a5);
            a6 = fmaf(gv, s2b[i] - psb[i], a6);
        }
        g_a7[ch * 8 + 0] = a0; g_a7[ch * 8 + 1] = a1; g_a7[ch * 8 + 2] = a2;
        g_a7[ch * 8 + 3] = a3; g_a7[ch * 8 + 4] = a4; g_a7[ch * 8 + 5] = a5;
        g_a7[ch * 8 + 6] = a6 + g1b[ch];
        g_a7[ch * 8 + 7] = 0.0f;
    }
}

// ---------------------------------------------------------------------------
// kNN: one WARP per query, 4 candidates per lane per step.
// Quarters processed sequentially in ascending index order (top_k ties).
// ---------------------------------------------------------------------------
__device__ __forceinline__ void knn_insert(unsigned m, float d2, int ibase, int lane,
                                           float& lv, int& li, float& tau)
{
    while (m) {
        int src = __ffs(m) - 1; m &= m - 1;
        float v  = __shfl_sync(FULLM, d2, src);
        int   vi = ibase + src;
        if (v < tau) {
            unsigned le = __ballot_sync(FULLM, lv <= v) & 0xFFFFu;
            int pos = __popc(le);
            float upv = __shfl_up_sync(FULLM, lv, 1);
            int   upi = __shfl_up_sync(FULLM, li, 1);
            if (lane == pos)      { lv = v;   li = vi;  }
            else if (lane > pos)  { lv = upv; li = upi; }
            tau = __shfl_sync(FULLM, lv, 15);
        }
    }
}

__global__ __launch_bounds__(256) void knn_kernel()
{
    const int gw   = (blockIdx.x * blockDim.x + threadIdx.x) >> 5;
    const int lane = threadIdx.x & 31;
    const int b    = gw >> 12;
    const int q    = gw & (NP - 1);

    const float4* cb = g_c4 + b * NP;
    const float4  qc = cb[q];

    float lv  = 3.4e38f;
    int   li  = 0;
    float tau = 3.4e38f;

    for (int t = 0; t < NP / 128; ++t) {
        const int j0 = t * 128 + lane;
        float4 c1 = __ldg(cb + j0);
        float4 c2 = __ldg(cb + j0 + 32);
        float4 c3 = __ldg(cb + j0 + 64);
        float4 c4 = __ldg(cb + j0 + 96);
        float d2a = __fsub_rn(__fadd_rn(qc.w, c1.w),
                              __fmul_rn(2.0f, qc.x * c1.x + qc.y * c1.y + qc.z * c1.z));
        float d2b = __fsub_rn(__fadd_rn(qc.w, c2.w),
                              __fmul_rn(2.0f, qc.x * c2.x + qc.y * c2.y + qc.z * c2.z));
        float d2c = __fsub_rn(__fadd_rn(qc.w, c3.w),
                              __fmul_rn(2.0f, qc.x * c3.x + qc.y * c3.y + qc.z * c3.z));
        float d2d = __fsub_rn(__fadd_rn(qc.w, c4.w),
                              __fmul_rn(2.0f, qc.x * c4.x + qc.y * c4.y + qc.z * c4.z));

        knn_insert(__ballot_sync(FULLM, d2a < tau), d2a, t * 128,      lane, lv, li, tau);
        knn_insert(__ballot_sync(FULLM, d2b < tau), d2b, t * 128 + 32, lane, lv, li, tau);
        knn_insert(__ballot_sync(FULLM, d2c < tau), d2c, t * 128 + 64, lane, lv, li, tau);
        knn_insert(__ballot_sync(FULLM, d2d < tau), d2d, t * 128 + 96, lane, lv, li, tau);
    }
    if (lane < KN) g_knn[((size_t)b * NP + q) * KN + lane] = li;
}

// ---------------------------------------------------------------------------
__device__ __forceinline__ void mma16816(float (&d)[4], uint a0, uint a1, uint a2, uint a3,
                                         uint b0, uint b1)
{
    asm volatile(
        "mma.sync.aligned.m16n8k16.row.col.f32.bf16.bf16.f32 "
        "{%0,%1,%2,%3}, {%4,%5,%6,%7}, {%8,%9}, {%0,%1,%2,%3};"
        : "+f"(d[0]), "+f"(d[1]), "+f"(d[2]), "+f"(d[3])
        : "r"(a0), "r"(a1), "r"(a2), "r"(a3), "r"(b0), "r"(b1));
}

#define ATT2_STRIDE 36   // uint4 per col row; 576B = 64 mod 128 -> conflict-free

template <int NG>
__device__ __forceinline__ void gamma_mma(
    const uint4* __restrict__ W, const float* __restrict__ bias,
    const uint4* __restrict__ att2v, int M0, int n0, int gid, int tig,
    float d[2][NG][4][4])
{
#pragma unroll
    for (int mt = 0; mt < 2; ++mt) {
        float b0 = bias[M0 + mt * 16 + gid];
        float b1 = bias[M0 + mt * 16 + gid + 8];
#pragma unroll
        for (int ng = 0; ng < NG; ++ng)
#pragma unroll
        for (int nt = 0; nt < 4; ++nt) {
            d[mt][ng][nt][0] = b0; d[mt][ng][nt][1] = b0;
            d[mt][ng][nt][2] = b1; d[mt][ng][nt][3] = b1;
        }
    }
#pragma unroll
    for (int ks = 0; ks < 8; ++ks) {
        const int wo = ks * 4 + tig;
        uint4 A0 = W[(M0 + gid) * 32 + wo];
        uint4 A1 = W[(M0 + gid + 8) * 32 + wo];
        uint4 A2 = W[(M0 + 16 + gid) * 32 + wo];
        uint4 A3 = W[(M0 + 16 + gid + 8) * 32 + wo];
#pragma unroll
        for (int ng = 0; ng < NG; ++ng)
#pragma unroll
        for (int nt = 0; nt < 4; ++nt) {
            int n = n0 + ng * 32 + nt * 8 + gid;
            uint4 bv = att2v[n * ATT2_STRIDE + wo];
            mma16816(d[0][ng][nt], A0.x, A1.x, A0.y, A1.y, bv.x, bv.y);  // Hh*Bh
            mma16816(d[0][ng][nt], A0.x, A1.x, A0.y, A1.y, bv.z, bv.w);  // Hh*Bl
            mma16816(d[0][ng][nt], A0.z, A1.z, A0.w, A1.w, bv.x, bv.y);  // Hl*Bh
            mma16816(d[1][ng][nt], A2.x, A3.x, A2.y, A3.y, bv.x, bv.y);
            mma16816(d[1][ng][nt], A2.x, A3.x, A2.y, A3.y, bv.z, bv.w);
            mma16816(d[1][ng][nt], A2.z, A3.z, A2.w, A3.w, bv.x, bv.y);
        }
    }
}

// ---------------------------------------------------------------------------
// phi_kernel: Y = g1_w @ (phi_w @ f + phi_b). Block = 32 points (512 CTAs).
// ---------------------------------------------------------------------------
__global__ __launch_bounds__(128) void phi_kernel(const float* __restrict__ features,
                                                  const float* __restrict__ phi_b)
{
    __shared__ __align__(16) char fsm[32 * 576];
    uint4*  f2v = (uint4*)fsm;
    ushort* f2u = (ushort*)fsm;

    const int t     = threadIdx.x;
    const int pbase = blockIdx.x * 32;
    const float4* fv = (const float4*)(features + (size_t)pbase * NC);

    // stage features (32 pts x 128 ch) split hi/lo into interleaved layout
#pragma unroll
    for (int it = 0; it < 8; ++it) {
        int li  = it * 128 + t;
        int col = li >> 5;
        int c4  = li & 31;
        float4 v = fv[li];
        int ch = c4 * 4;
        int ks = ch >> 4, ii = ch & 15;                       // ii in {0,4,8,12}
        int p  = ((ii >> 1) & 3) * 4 + ((ii >> 3) << 1);
        int idx = col * 288 + (ks * 4 + (p >> 2)) * 8 + (p & 3);
        __nv_bfloat16 h0 = __float2bfloat16(v.x), h1 = __float2bfloat16(v.y);
        __nv_bfloat16 h2 = __float2bfloat16(v.z), h3 = __float2bfloat16(v.w);
        __nv_bfloat16 l0 = __float2bfloat16(v.x - __bfloat162float(h0));
        __nv_bfloat16 l1 = __float2bfloat16(v.y - __bfloat162float(h1));
        __nv_bfloat16 l2 = __float2bfloat16(v.z - __bfloat162float(h2));
        __nv_bfloat16 l3 = __float2bfloat16(v.w - __bfloat162float(h3));
        *(uint*)&f2u[idx]      = (uint)__bfloat16_as_ushort(h0) | ((uint)__bfloat16_as_ushort(h1) << 16);
        *(uint*)&f2u[idx + 4]  = (uint)__bfloat16_as_ushort(l0) | ((uint)__bfloat16_as_ushort(l1) << 16);
        *(uint*)&f2u[idx + 8]  = (uint)__bfloat16_as_ushort(h2) | ((uint)__bfloat16_as_ushort(h3) << 16);
        *(uint*)&f2u[idx + 12] = (uint)__bfloat16_as_ushort(l2) | ((uint)__bfloat16_as_ushort(l3) << 16);
    }
    __syncthreads();

    const int wid = t >> 5, lane = t & 31;
    const int gid = lane >> 2, tig = lane & 3;
    const int M0  = wid * 32;

    float d[2][1][4][4];
    gamma_mma<1>(g_wpi, phi_b, f2v, M0, 0, gid, tig, d);     // xi
    __syncthreads();   // all warps done reading staged features

    // scatter xi (split) back into f2 layout: [col=point][k=channel]
#pragma unroll
    for (int mt = 0; mt < 2; ++mt)
#pragma unroll
    for (int nt = 0; nt < 4; ++nt)
#pragma unroll
    for (int e = 0; e < 4; ++e) {
        float v = d[mt][0][nt][e];
        int n    = nt * 8 + 2 * tig + (e & 1);
        int mrow = M0 + mt * 16 + gid + 8 * (e >> 1);
        int ks2 = mrow >> 4, i2 = mrow & 15;
        int p2 = ((i2 >> 1) & 3) * 4 + (i2 & 1) + ((i2 >> 3) << 1);
        int idx = n * 288 + (ks2 * 4 + (p2 >> 2)) * 8 + (p2 & 3);
        __nv_bfloat16 h = __float2bfloat16(v);
        f2u[idx]     = __bfloat16_as_ushort(h);
        f2u[idx + 4] = __bfloat16_as_ushort(__float2bfloat16(v - __bfloat162float(h)));
    }
    __syncthreads();

    gamma_mma<1>(g_w1i, g_zeros, f2v, M0, 0, gid, tig, d);   // Y = g1 @ xi

#pragma unroll
    for (int mt = 0; mt < 2; ++mt)
#pragma unroll
    for (int nt = 0; nt < 4; ++nt) {
        int m = M0 + mt * 16 + gid;
        int n = nt * 8 + 2 * tig;
        size_t r0 = (size_t)(pbase + n) * NC;
        g_y[r0 + m]            = d[mt][0][nt][0];
        g_y[r0 + NC + m]       = d[mt][0][nt][1];
        g_y[r0 + m + 8]        = d[mt][0][nt][2];
        g_y[r0 + NC + m + 8]   = d[mt][0][nt][3];
    }
}

// ---------------------------------------------------------------------------
// Fused point-transformer. Block = 8 points (128 cols), 256 threads, 8 warps.
// ---------------------------------------------------------------------------
// dynamic smem layout (bytes)
#define SM_ATT2 0                        // uint4 [128][36] = 73728; aliased by att_f
#define SM_Y    73728                    // float [8][128]  = 4096
#define SM_G    (SM_Y + 4096)            // float4 [128*2]  = 4096
#define SM_KC   (SM_G + 4096)            // float4 [128]    = 2048
#define SM_QC   (SM_KC + 2048)           // float4 [8]
#define SM_SMP  (SM_QC + 128)            // float [2][128]
#define SM_SMS  (SM_SMP + 1024)
#define SM_SMI  (SM_SMS + 1024)          // float [128]
#define SM_TOTAL (SM_SMI + 512)

__global__ __launch_bounds__(256, 2) void pt_kernel(
    const float* __restrict__ g2_b,
    const float* __restrict__ s1_w,   const float* __restrict__ s1_b,
    const float* __restrict__ s2_w,   const float* __restrict__ s2_b,
    const float* __restrict__ alpha_w, const float* __restrict__ alpha_b,
    float* __restrict__ out)
{
    extern __shared__ __align__(16) char sm[];
    uint4*  att2v = (uint4*)(sm + SM_ATT2);
    ushort* att2u = (ushort*)(sm + SM_ATT2);            // row stride 288 ushorts
    float (*att_f)[130] = (float(*)[130])(sm + SM_ATT2); // alias (att2 dead by then)
    float (*ysh)[NC]   = (float(*)[NC])(sm + SM_Y);
    float4* gsh        = (float4*)(sm + SM_G);          // [128][2] float4
    float4* kc         = (float4*)(sm + SM_KC);
    float4* qc         = (float4*)(sm + SM_QC);
    float (*smp)[128]  = (float(*)[128])(sm + SM_SMP);
    float (*sms)[128]  = (float(*)[128])(sm + SM_SMS);
    float* sminv       = (float*)(sm + SM_SMI);

    const int t    = threadIdx.x;
    const int c    = t & 63;
    const int cg   = t >> 6;              // 0..3 -> cols cg*32..+31, points 2cg,2cg+1
    const int pn0  = blockIdx.x * 8;
    const int b    = pn0 >> 12;
    const int n0_  = pn0 & (NP - 1);
    const int base = b * NP + n0_;

    // ---- loads (Y coalesced: one float4 per thread) ----
    {
        int p = t >> 5, f4 = t & 31;
        ((float4*)ysh[p])[f4] = ((const float4*)(g_y + (size_t)(base + p) * NC))[f4];
    }
    if (t < 128) {
        int p  = t >> 4;
        int id = g_knn[(size_t)(base + p) * KN + (t & 15)];
        kc[t]  = g_c4[b * NP + id];
    }
    if (t < 8) qc[t] = g_c4[base + t];
    __syncthreads();

    // ---- g[col] = [kc, h(col), 1, 0] computed once per column ----
    if (t < 128) {
        float4 cc = kc[t];
        float4 qv = qc[t >> 4];
        float rx = qv.x - cc.x, ry = qv.y - cc.y, rz = qv.z - cc.z;
        float h0 = fmaxf(s1_w[0] * rx + s1_w[1] * ry + s1_w[2] * rz + s1_b[0], 0.0f);
        float h1 = fmaxf(s1_w[3] * rx + s1_w[4] * ry + s1_w[5] * rz + s1_b[1], 0.0f);
        float h2 = fmaxf(s1_w[6] * rx + s1_w[7] * ry + s1_w[8] * rz + s1_b[2], 0.0f);
        gsh[t * 2]     = make_float4(cc.x, cc.y, cc.z, h0);
        gsh[t * 2 + 1] = make_float4(h1, h2, 1.0f, 0.0f);
    }
    __syncthreads();

    // ---- layer 1 (folded): l1 = relu(A7.g + Y), split into att2 ----
    const int ch0 = 2 * c, ch1 = 2 * c + 1;
    {
        const float4* a7v = (const float4*)g_a7;
        float4 a0l = a7v[ch0 * 2], a0h = a7v[ch0 * 2 + 1];
        float4 a1l = a7v[ch1 * 2], a1h = a7v[ch1 * 2 + 1];
        const float y00 = ysh[cg * 2 + 0][ch0], y01 = ysh[cg * 2 + 1][ch0];
        const float y10 = ysh[cg * 2 + 0][ch1], y11 = ysh[cg * 2 + 1][ch1];
        const int ksq = ch0 >> 4;
        const int iq  = ch0 & 15;                              // even
        const int pq  = ((iq >> 1) & 3) * 4 + ((iq >> 3) << 1);
        const int hbase = (ksq * 4 + (pq >> 2)) * 8 + (pq & 3);
#pragma unroll
        for (int jj = 0; jj < 32; ++jj) {
            int col = cg * 32 + jj;
            float4 gl = gsh[col * 2], gh = gsh[col * 2 + 1];
            float v0 = a0l.x * gl.x + a0l.y * gl.y + a0l.z * gl.z + a0l.w * gl.w
                     + a0h.x * gh.x + a0h.y * gh.y + a0h.z
                     + ((jj & 16) ? y01 : y00);
            float v1 = a1l.x * gl.x + a1l.y * gl.y + a1l.z * gl.z + a1l.w * gl.w
                     + a1h.x * gh.x + a1h.y * gh.y + a1h.z
                     + ((jj & 16) ? y11 : y10);
            v0 = fmaxf(v0, 0.0f);
            v1 = fmaxf(v1, 0.0f);
            __nv_bfloat16 vh0 = __float2bfloat16(v0);
            __nv_bfloat16 vh1 = __float2bfloat16(v1);
            __nv_bfloat16 vl0 = __float2bfloat16(v0 - __bfloat162float(vh0));
            __nv_bfloat16 vl1 = __float2bfloat16(v1 - __bfloat162float(vh1));
            int idx = col * 288 + hbase;
            *(uint*)&att2u[idx]     = (uint)__bfloat16_as_ushort(vh0) | ((uint)__bfloat16_as_ushort(vh1) << 16);
            *(uint*)&att2u[idx + 4] = (uint)__bfloat16_as_ushort(vl0) | ((uint)__bfloat16_as_ushort(vl1) << 16);
        }
    }
    __syncthreads();

    const int wid = t >> 5, lane = t & 31;
    const int gid = lane >> 2, tig = lane & 3;
    const int M0  = (wid & 3) * 32;
    const int nc0 = (wid >> 2) * 64;

    float d[2][2][4][4];

    // ================= gamma layer 2 (MMA; fp32 out to att_f alias) =========
    gamma_mma<2>(g_w2i, g2_b, att2v, M0, nc0, gid, tig, d);
    __syncthreads();   // att2 fully read by ALL warps before aliased overwrite
#pragma unroll
    for (int mt = 0; mt < 2; ++mt)
#pragma unroll
    for (int ng = 0; ng < 2; ++ng)
#pragma unroll
    for (int nt = 0; nt < 4; ++nt) {
        int m = M0 + mt * 16 + gid;
        int n = nc0 + ng * 32 + nt * 8 + 2 * tig;
        *(float2*)&att_f[m][n]     = make_float2(d[mt][ng][nt][0], d[mt][ng][nt][1]);
        *(float2*)&att_f[m + 8][n] = make_float2(d[mt][ng][nt][2], d[mt][ng][nt][3]);
    }
    __syncthreads();

    // ---- softmax over channels (rows), per column ----
    {
        int col = t & 127, h = t >> 7;
        float m = -3.4e38f;
#pragma unroll 8
        for (int i = h * 64; i < h * 64 + 64; ++i) m = fmaxf(m, att_f[i][col]);
        smp[h][col] = m;
        __syncthreads();
        m = fmaxf(smp[0][col], smp[1][col]);
        float s = 0.0f;
#pragma unroll 4
        for (int i = h * 64; i < h * 64 + 64; ++i) {
            float e = __expf(att_f[i][col] - m);
            att_f[i][col] = e;
            s += e;
        }
        sms[h][col] = s;
        __syncthreads();
        if (t < 128) sminv[col] = 1.0f / (sms[0][col] + sms[1][col]);
        __syncthreads();
    }

    // ---- epilogue: out = sum_k softmax * (V7.g) ----
    {
        const int oa = c, ob = c + 64;
        const float aa0 = alpha_w[oa * 3], aa1 = alpha_w[oa * 3 + 1], aa2 = alpha_w[oa * 3 + 2];
        const float ab0 = alpha_w[ob * 3], ab1 = alpha_w[ob * 3 + 1], ab2 = alpha_w[ob * 3 + 2];
        const float s2a0 = s2_w[oa * 3], s2a1 = s2_w[oa * 3 + 1], s2a2 = s2_w[oa * 3 + 2];
        const float s2b0 = s2_w[ob * 3], s2b1 = s2_w[ob * 3 + 1], s2b2 = s2_w[ob * 3 + 2];
        const float ca = alpha_b[oa] + s2_b[oa];
        const float cb = alpha_b[ob] + s2_b[ob];

        float o0a = 0.0f, o1a = 0.0f, o0b = 0.0f, o1b = 0.0f;
#pragma unroll
        for (int jj = 0; jj < 32; ++jj) {
            int col = cg * 32 + jj;
            float4 gl = gsh[col * 2], gh = gsh[col * 2 + 1];
            float va = aa0 * gl.x + aa1 * gl.y + aa2 * gl.z + s2a0 * gl.w
                     + s2a1 * gh.x + s2a2 * gh.y + ca;
            float vb = ab0 * gl.x + ab1 * gl.y + ab2 * gl.z + s2b0 * gl.w
                     + s2b1 * gh.x + s2b2 * gh.y + cb;
            float iv = sminv[col];
            float ea = att_f[oa][col] * iv;
            float eb = att_f[ob][col] * iv;
            if (jj < 16) { o0a += ea * va; o0b += eb * vb; }
            else         { o1a += ea * va; o1b += eb * vb; }
        }
        int p0 = cg * 2;
        out[(size_t)(base + p0) * NC + oa]     = o0a;
        out[(size_t)(base + p0) * NC + ob]     = o0b;
        out[(size_t)(base + p0 + 1) * NC + oa] = o1a;
        out[(size_t)(base + p0 + 1) * NC + ob] = o1b;
    }
}

// ---------------------------------------------------------------------------
extern "C" void kernel_launch(void* const* d_in, const int* in_sizes, int n_in,
                              void* d_out, int out_size)
{
    const float* coords   = (const float*)d_in[0];
    const float* features = (const float*)d_in[1];
    const float* phi_w    = (const float*)d_in[2];
    const float* phi_b    = (const float*)d_in[3];
    const float* psi_w    = (const float*)d_in[4];
    const float* psi_b    = (const float*)d_in[5];
    const float* g1_w     = (const float*)d_in[6];
    const float* g1_b     = (const float*)d_in[7];
    const float* g2_w     = (const float*)d_in[8];
    const float* g2_b     = (const float*)d_in[9];
    const float* s1_w     = (const float*)d_in[10];
    const float* s1_b     = (const float*)d_in[11];
    const float* s2_w     = (const float*)d_in[12];
    const float* s2_b     = (const float*)d_in[13];
    const float* alpha_w  = (const float*)d_in[14];
    const float* alpha_b  = (const float*)d_in[15];
    float* out = (float*)d_out;

    cudaFuncSetAttribute(pt_kernel, cudaFuncAttributeMaxDynamicSharedMemorySize, SM_TOTAL);

    setup_kernel<<<129, 256>>>(coords, g1_w, g2_w, phi_w,
                               g1_b, psi_w, psi_b, s2_w, s2_b);
    phi_kernel<<<NB * NP / 32, 128>>>(features, phi_b);
    knn_kernel<<<NB * NP * 32 / 256, 256>>>();
    pt_kernel<<<NB * NP / 8, 256, SM_TOTAL>>>(g2_b,
                                              s1_w, s1_b, s2_w, s2_b,
                                              alpha_w, alpha_b, out);
}